// round 5
// baseline (speedup 1.0000x reference)
#include <cuda_runtime.h>
#include <cuda_bf16.h>
#include <cstdint>

#define NN 50000
#define EE 800000
#define IN_CH 256
#define HID 128
#define LAT 64
#define NB_SCAN ((NN + 255) / 256)   // 196

// ---------------- scratch (device globals; no allocation allowed) -------------
__device__ int   g_anynz;              // dtype probe: nonzero => edge_index is int32
__device__ int   g_src[EE];            // unpacked edge sources
__device__ int   g_dst[EE];            // unpacked edge destinations
__device__ int   g_cnt[NN];            // in-degree (no self loop)
__device__ int   g_cursor[NN];         // bucket cursors
__device__ int   g_start[NN];          // exclusive offsets
__device__ int   g_incl[NN];           // per-block inclusive scan
__device__ int   g_bsum[NB_SCAN];      // block sums
__device__ int   g_csr_src[EE];        // src indices grouped by dst
__device__ float g_dinv[NN];           // deg^-1/2 (deg includes self loop)
__device__ float g_h1[(size_t)NN * HID];
__device__ float g_o1[(size_t)NN * HID];
__device__ float g_h2[(size_t)NN * LAT];

// ---------------- dtype probe + edge unpack -----------------------------------
__global__ void k_reset(int* cnt, int* cursor, int n) {
    int i = blockIdx.x * blockDim.x + threadIdx.x;
    if (i == 0) g_anynz = 0;
    if (i < n) { cnt[i] = 0; cursor[i] = 0; }
}

// Sample odd int32 words. int64 layout => high words => all zero.
// int32 layout => random indices => almost surely some nonzero.
__global__ void k_detect(const int* __restrict__ ei32, int e) {
    int t = threadIdx.x + blockIdx.x * blockDim.x;   // 1024 samples
    if (t >= 1024) return;
    long long k = (long long)t * (e / 1024);         // k in [0, e)
    int w = ei32[2 * k + 1];                         // odd word
    if (w != 0) atomicOr(&g_anynz, 1);
}

__global__ void k_convert(const int* __restrict__ ei32, int* src, int* dst, int e) {
    int i = blockIdx.x * blockDim.x + threadIdx.x;
    if (i >= e) return;
    if (g_anynz == 0) {            // int64: little-endian lo word carries the index
        src[i] = ei32[2 * (size_t)i];
        dst[i] = ei32[2 * ((size_t)e + i)];
    } else {                       // int32
        src[i] = ei32[i];
        dst[i] = ei32[e + i];
    }
}

// ---------------- CSR build ---------------------------------------------------
__global__ void k_hist(const int* __restrict__ dst, int* cnt, int e) {
    int i = blockIdx.x * blockDim.x + threadIdx.x;
    if (i < e) atomicAdd(&cnt[dst[i]], 1);
}

__global__ void k_scan_a(const int* __restrict__ cnt, int* incl, int* bsum, int n) {
    __shared__ int s[256];
    int i = blockIdx.x * 256 + threadIdx.x;
    int v = (i < n) ? cnt[i] : 0;
    s[threadIdx.x] = v;
    __syncthreads();
    for (int off = 1; off < 256; off <<= 1) {
        int t = (threadIdx.x >= off) ? s[threadIdx.x - off] : 0;
        __syncthreads();
        s[threadIdx.x] += t;
        __syncthreads();
    }
    if (i < n) incl[i] = s[threadIdx.x];
    if (threadIdx.x == 255) bsum[blockIdx.x] = s[255];
}

__global__ void k_scan_b(int* bsum, int nb) {
    __shared__ int s[256];
    int v = (threadIdx.x < nb) ? bsum[threadIdx.x] : 0;
    s[threadIdx.x] = v;
    __syncthreads();
    for (int off = 1; off < 256; off <<= 1) {
        int t = (threadIdx.x >= off) ? s[threadIdx.x - off] : 0;
        __syncthreads();
        s[threadIdx.x] += t;
        __syncthreads();
    }
    if (threadIdx.x < nb) bsum[threadIdx.x] = s[threadIdx.x];
}

__global__ void k_scan_c(const int* __restrict__ cnt, const int* __restrict__ incl,
                         const int* __restrict__ bsum, int* start,
                         float* dinv, int n) {
    int i = blockIdx.x * 256 + threadIdx.x;
    if (i >= n) return;
    int bexcl = (blockIdx.x > 0) ? bsum[blockIdx.x - 1] : 0;
    start[i] = bexcl + incl[i] - cnt[i];
    dinv[i] = rsqrtf((float)(cnt[i] + 1));
}

__global__ void k_fill(const int* __restrict__ src, const int* __restrict__ dst,
                       const int* __restrict__ start, int* cursor, int* csr, int e) {
    int i = blockIdx.x * blockDim.x + threadIdx.x;
    if (i >= e) return;
    int d = dst[i];
    int pos = start[d] + atomicAdd(&cursor[d], 1);
    csr[pos] = src[i];
}

// ---------------- tiled fp32 GEMM: C = (reluA?relu(A):A) @ B ------------------
template <int BM, int BN, int BK, int TM, int TN, bool RELU_A>
__global__ void __launch_bounds__(256) gemm_tiled(
    const float* __restrict__ A, const float* __restrict__ B,
    float* __restrict__ C, int M, int N, int K)
{
    static_assert(TM == 4, "");
    static_assert((BM / TM) * (BN / TN) == 256, "");
    __shared__ float As[BK][BM];
    __shared__ float Bs[BK][BN];

    const int tid = threadIdx.x;
    const int tx  = tid % (BN / TN);
    const int ty  = tid / (BN / TN);
    const int m0  = blockIdx.x * BM;

    float acc[TM][TN];
#pragma unroll
    for (int i = 0; i < TM; i++)
#pragma unroll
        for (int j = 0; j < TN; j++) acc[i][j] = 0.0f;

    for (int k0 = 0; k0 < K; k0 += BK) {
        {
            int r = tid / (BK / 4);
            int c = (tid % (BK / 4)) * 4;
            float4 v = make_float4(0.f, 0.f, 0.f, 0.f);
            if (m0 + r < M)
                v = *(const float4*)(A + (size_t)(m0 + r) * K + k0 + c);
            if (RELU_A) {
                v.x = fmaxf(v.x, 0.f); v.y = fmaxf(v.y, 0.f);
                v.z = fmaxf(v.z, 0.f); v.w = fmaxf(v.w, 0.f);
            }
            As[c + 0][r] = v.x; As[c + 1][r] = v.y;
            As[c + 2][r] = v.z; As[c + 3][r] = v.w;
        }
        for (int idx = tid; idx < BK * BN / 4; idx += 256) {
            int r = idx / (BN / 4);
            int c = (idx % (BN / 4)) * 4;
            *(float4*)&Bs[r][c] = *(const float4*)(B + (size_t)(k0 + r) * N + c);
        }
        __syncthreads();

#pragma unroll
        for (int k = 0; k < BK; k++) {
            float a[TM], b[TN];
            *(float4*)a = *(const float4*)&As[k][ty * TM];
#pragma unroll
            for (int j = 0; j < TN; j += 4)
                *(float4*)&b[j] = *(const float4*)&Bs[k][tx * TN + j];
#pragma unroll
            for (int i = 0; i < TM; i++)
#pragma unroll
                for (int j = 0; j < TN; j++)
                    acc[i][j] = fmaf(a[i], b[j], acc[i][j]);
        }
        __syncthreads();
    }

#pragma unroll
    for (int i = 0; i < TM; i++) {
        int row = m0 + ty * TM + i;
        if (row < M) {
#pragma unroll
            for (int j = 0; j < TN; j += 4)
                *(float4*)(C + (size_t)row * N + tx * TN + j) = *(float4*)&acc[i][j];
        }
    }
}

// ---------------- gather aggregation, 128 feats: one warp per dst node --------
__global__ void __launch_bounds__(256) k_agg128(
    const int* __restrict__ start, const int* __restrict__ cnt,
    const int* __restrict__ csr, const float* __restrict__ dinv,
    const float* __restrict__ h, const float* __restrict__ bias,
    float* __restrict__ out, int n)
{
    int warp = (blockIdx.x * blockDim.x + threadIdx.x) >> 5;
    int lane = threadIdx.x & 31;
    if (warp >= n) return;
    const int d = warp;
    float dd = dinv[d];
    int beg = start[d];
    int num = cnt[d];

    float4 hv = *(const float4*)(h + (size_t)d * 128 + lane * 4);
    float4 bv = *(const float4*)(bias + lane * 4);
    float sd = dd * dd;
    float4 acc;
    acc.x = fmaf(sd, hv.x, bv.x); acc.y = fmaf(sd, hv.y, bv.y);
    acc.z = fmaf(sd, hv.z, bv.z); acc.w = fmaf(sd, hv.w, bv.w);

    for (int j = 0; j < num; j++) {
        int s = __ldg(&csr[beg + j]);
        float nrm = dd * __ldg(&dinv[s]);
        float4 v = __ldg((const float4*)(h + (size_t)s * 128) + lane);
        acc.x = fmaf(nrm, v.x, acc.x); acc.y = fmaf(nrm, v.y, acc.y);
        acc.z = fmaf(nrm, v.z, acc.z); acc.w = fmaf(nrm, v.w, acc.w);
    }
    *(float4*)(out + (size_t)d * 128 + lane * 4) = acc;
}

// ---------------- gather aggregation, 64 feats + fused final relu -------------
__global__ void __launch_bounds__(256) k_agg64_relu(
    const int* __restrict__ start, const int* __restrict__ cnt,
    const int* __restrict__ csr, const float* __restrict__ dinv,
    const float* __restrict__ h, const float* __restrict__ bias,
    float* __restrict__ out, int n)
{
    int warp = (blockIdx.x * blockDim.x + threadIdx.x) >> 5;
    int lane = threadIdx.x & 31;
    if (warp >= n) return;
    const int d = warp;
    float dd = dinv[d];
    int beg = start[d];
    int num = cnt[d];

    float2 hv = *(const float2*)(h + (size_t)d * 64 + lane * 2);
    float2 bv = *(const float2*)(bias + lane * 2);
    float sd = dd * dd;
    float2 acc;
    acc.x = fmaf(sd, hv.x, bv.x); acc.y = fmaf(sd, hv.y, bv.y);

    for (int j = 0; j < num; j++) {
        int s = __ldg(&csr[beg + j]);
        float nrm = dd * __ldg(&dinv[s]);
        float2 v = __ldg((const float2*)(h + (size_t)s * 64) + lane);
        acc.x = fmaf(nrm, v.x, acc.x); acc.y = fmaf(nrm, v.y, acc.y);
    }
    acc.x = fmaxf(acc.x, 0.f);
    acc.y = fmaxf(acc.y, 0.f);
    *(float2*)(out + (size_t)d * 64 + lane * 2) = acc;
}

// ==============================================================================
extern "C" void kernel_launch(void* const* d_in, const int* in_sizes, int n_in,
                              void* d_out, int out_size)
{
    const float* x    = (const float*)d_in[0];   // [N, 256]
    const int*   ei32 = (const int*)d_in[1];     // [2, E] int32 OR int64 (probed)
    const float* W1   = (const float*)d_in[2];   // [256, 128]
    const float* b1   = (const float*)d_in[3];   // [128]
    const float* W2   = (const float*)d_in[4];   // [128, 64]
    const float* b2   = (const float*)d_in[5];   // [64]
    float*       out  = (float*)d_out;           // [N, 64]

    const int n = in_sizes[0] / IN_CH;   // 50000
    const int e = in_sizes[1] / 2;       // 800000

    int *src, *dst, *cnt, *cursor, *startp, *incl, *bsum, *csr;
    float *dinv, *h1, *o1, *h2;
    cudaGetSymbolAddress((void**)&src,    g_src);
    cudaGetSymbolAddress((void**)&dst,    g_dst);
    cudaGetSymbolAddress((void**)&cnt,    g_cnt);
    cudaGetSymbolAddress((void**)&cursor, g_cursor);
    cudaGetSymbolAddress((void**)&startp, g_start);
    cudaGetSymbolAddress((void**)&incl,   g_incl);
    cudaGetSymbolAddress((void**)&bsum,   g_bsum);
    cudaGetSymbolAddress((void**)&csr,    g_csr_src);
    cudaGetSymbolAddress((void**)&dinv,   g_dinv);
    cudaGetSymbolAddress((void**)&h1,     g_h1);
    cudaGetSymbolAddress((void**)&o1,     g_o1);
    cudaGetSymbolAddress((void**)&h2,     g_h2);

    const int T = 256;
    const int nb = (n + T - 1) / T;
    const int eb = (e + T - 1) / T;

    // --- dtype probe + unpack edge_index ---
    k_reset<<<nb, T>>>(cnt, cursor, n);
    k_detect<<<4, T>>>(ei32, e);
    k_convert<<<eb, T>>>(ei32, src, dst, e);

    // --- CSR build + norms ---
    k_hist<<<eb, T>>>(dst, cnt, e);
    k_scan_a<<<nb, T>>>(cnt, incl, bsum, n);
    k_scan_b<<<1, T>>>(bsum, nb);
    k_scan_c<<<nb, T>>>(cnt, incl, bsum, startp, dinv, n);
    k_fill<<<eb, T>>>(src, dst, startp, cursor, csr, e);

    // --- layer 1: h1 = x @ W1; o1 = gcn_agg(h1) ---
    gemm_tiled<64, 128, 16, 4, 8, false>
        <<<(n + 63) / 64, 256>>>(x, W1, h1, n, HID, IN_CH);
    k_agg128<<<(n * 32 + T - 1) / T, T>>>(startp, cnt, csr, dinv, h1, b1, o1, n);

    // --- layer 2: h2 = relu(o1) @ W2; out = relu(gcn_agg(h2)) ---
    gemm_tiled<64, 64, 16, 4, 4, true>
        <<<(n + 63) / 64, 256>>>(o1, W2, h2, n, LAT, HID);
    k_agg64_relu<<<(n * 32 + T - 1) / T, T>>>(startp, cnt, csr, dinv, h2, b2, out, n);
}

// round 7
// speedup vs baseline: 1.7164x; 1.7164x over previous
#include <cuda_runtime.h>
#include <cuda_bf16.h>
#include <cstdint>

#define NN 50000
#define EE 800000
#define IN_CH 256
#define HID 128
#define LAT 64
#define NB_SCAN ((NN + 255) / 256)   // 196

// ---------------- scratch (device globals; no allocation allowed) -------------
__device__ int   g_anynz;
__device__ int   g_src[EE];
__device__ int   g_dst[EE];
__device__ int   g_cnt[NN];
__device__ int   g_cursor[NN];
__device__ int   g_start[NN];
__device__ int   g_incl[NN];
__device__ int   g_bsum[NB_SCAN];
__device__ int   g_csr_src[EE];
__device__ float g_dinv[NN];
__device__ float g_h1[(size_t)NN * HID];
__device__ float g_o1[(size_t)NN * HID];
__device__ float g_h2[(size_t)NN * LAT];

// ---------------- dtype probe + edge unpack + fused histogram -----------------
__global__ void k_reset(int* cnt, int* cursor, int n) {
    int i = blockIdx.x * blockDim.x + threadIdx.x;
    if (i == 0) g_anynz = 0;
    if (i < n) { cnt[i] = 0; cursor[i] = 0; }
}

__global__ void k_detect(const int* __restrict__ ei32, int e) {
    int t = threadIdx.x + blockIdx.x * blockDim.x;
    if (t >= 1024) return;
    long long k = (long long)t * (e / 1024);
    if (ei32[2 * k + 1] != 0) atomicOr(&g_anynz, 1);
}

__global__ void k_convert(const int* __restrict__ ei32, int* src, int* dst,
                          int* cnt, int e) {
    int i = blockIdx.x * blockDim.x + threadIdx.x;
    if (i >= e) return;
    int s, d;
    if (g_anynz == 0) {            // int64 little-endian: low word carries index
        s = ei32[2 * (size_t)i];
        d = ei32[2 * ((size_t)e + i)];
    } else {                       // int32
        s = ei32[i];
        d = ei32[e + i];
    }
    src[i] = s;
    dst[i] = d;
    atomicAdd(&cnt[d], 1);
}

// ---------------- CSR build ---------------------------------------------------
__global__ void k_scan_a(const int* __restrict__ cnt, int* incl, int* bsum, int n) {
    __shared__ int s[256];
    int i = blockIdx.x * 256 + threadIdx.x;
    int v = (i < n) ? cnt[i] : 0;
    s[threadIdx.x] = v;
    __syncthreads();
    for (int off = 1; off < 256; off <<= 1) {
        int t = (threadIdx.x >= off) ? s[threadIdx.x - off] : 0;
        __syncthreads();
        s[threadIdx.x] += t;
        __syncthreads();
    }
    if (i < n) incl[i] = s[threadIdx.x];
    if (threadIdx.x == 255) bsum[blockIdx.x] = s[255];
}

__global__ void k_scan_b(int* bsum, int nb) {
    __shared__ int s[256];
    int v = (threadIdx.x < nb) ? bsum[threadIdx.x] : 0;
    s[threadIdx.x] = v;
    __syncthreads();
    for (int off = 1; off < 256; off <<= 1) {
        int t = (threadIdx.x >= off) ? s[threadIdx.x - off] : 0;
        __syncthreads();
        s[threadIdx.x] += t;
        __syncthreads();
    }
    if (threadIdx.x < nb) bsum[threadIdx.x] = s[threadIdx.x];
}

__global__ void k_scan_c(const int* __restrict__ cnt, const int* __restrict__ incl,
                         const int* __restrict__ bsum, int* start,
                         float* dinv, int n) {
    int i = blockIdx.x * 256 + threadIdx.x;
    if (i >= n) return;
    int bexcl = (blockIdx.x > 0) ? bsum[blockIdx.x - 1] : 0;
    start[i] = bexcl + incl[i] - cnt[i];
    dinv[i] = rsqrtf((float)(cnt[i] + 1));
}

__global__ void k_fill(const int* __restrict__ src, const int* __restrict__ dst,
                       const int* __restrict__ start, int* cursor, int* csr, int e) {
    int i = blockIdx.x * blockDim.x + threadIdx.x;
    if (i >= e) return;
    int d = dst[i];
    int pos = start[d] + atomicAdd(&cursor[d], 1);
    csr[pos] = src[i];
}

// ---------------- 3xTF32 tensor-core GEMM: C[M,BN] = op(A)[M,K] @ B[K,BN] -----
// BM=128, BK=32, 256 threads = 8 warps in 4x2 grid; warp tile 32 x (BN/2).
// Error-compensated: a*b ~= ahi*bhi + ahi*blo + alo*bhi, hi = truncate-13-bits.
__device__ __forceinline__ void mma_tf32(float4& d,
                                         uint32_t a0, uint32_t a1, uint32_t a2, uint32_t a3,
                                         uint32_t b0, uint32_t b1) {
    asm volatile(
        "mma.sync.aligned.m16n8k8.row.col.f32.tf32.tf32.f32 "
        "{%0,%1,%2,%3}, {%4,%5,%6,%7}, {%8,%9}, {%0,%1,%2,%3};"
        : "+f"(d.x), "+f"(d.y), "+f"(d.z), "+f"(d.w)
        : "r"(a0), "r"(a1), "r"(a2), "r"(a3), "r"(b0), "r"(b1));
}

__device__ __forceinline__ void split_tf32(float f, uint32_t& hi, uint32_t& lo) {
    uint32_t h = __float_as_uint(f) & 0xFFFFE000u;   // exact truncation
    hi = h;
    lo = __float_as_uint(f - __uint_as_float(h));    // exact residual
}

template <int BN, bool RELU_A>
__global__ void __launch_bounds__(256) gemm_3xtf32(
    const float* __restrict__ A, const float* __restrict__ B,
    float* __restrict__ C, int M, int K)
{
    constexpr int BM = 128, BK = 32;
    constexpr int NT = BN / 16;            // n8 tiles per warp (8 or 4)
    __shared__ float As[BM][BK + 4];       // [m][k], pad 4
    __shared__ float Bs[BK][BN + 8];       // [k][n], pad 8

    const int tid    = threadIdx.x;
    const int warp   = tid >> 5;
    const int lane   = tid & 31;
    const int warp_m = warp & 3;
    const int warp_n = warp >> 2;
    const int m0     = blockIdx.x * BM;
    const int qr     = lane >> 2;          // 0..7
    const int qc     = lane & 3;           // 0..3

    float4 acc[2][NT];
#pragma unroll
    for (int i = 0; i < 2; i++)
#pragma unroll
        for (int j = 0; j < NT; j++) acc[i][j] = make_float4(0.f, 0.f, 0.f, 0.f);

    for (int k0 = 0; k0 < K; k0 += BK) {
        // --- A tile: 128x32 = 1024 float4, 4 per thread, coalesced ---
#pragma unroll
        for (int i = 0; i < 4; i++) {
            int idx = tid + i * 256;
            int m   = idx >> 3;
            int k4  = (idx & 7) << 2;
            float4 v = make_float4(0.f, 0.f, 0.f, 0.f);
            if (m0 + m < M)
                v = *(const float4*)(A + (size_t)(m0 + m) * K + k0 + k4);
            if (RELU_A) {
                v.x = fmaxf(v.x, 0.f); v.y = fmaxf(v.y, 0.f);
                v.z = fmaxf(v.z, 0.f); v.w = fmaxf(v.w, 0.f);
            }
            *(float4*)&As[m][k4] = v;
        }
        // --- B tile: 32xBN, BN/32 float4 per thread ---
#pragma unroll
        for (int i = 0; i < BN / 32; i++) {
            int idx = tid + i * 256;
            int k   = idx / (BN / 4);
            int n4  = (idx % (BN / 4)) << 2;
            *(float4*)&Bs[k][n4] = *(const float4*)(B + (size_t)(k0 + k) * BN + n4);
        }
        __syncthreads();

#pragma unroll
        for (int ks = 0; ks < 4; ks++) {
            const int c = ks * 8;
            uint32_t ah[2][4], al[2][4];
#pragma unroll
            for (int mt = 0; mt < 2; mt++) {
                int r = warp_m * 32 + mt * 16 + qr;
                split_tf32(As[r][c + qc],         ah[mt][0], al[mt][0]);
                split_tf32(As[r + 8][c + qc],     ah[mt][1], al[mt][1]);
                split_tf32(As[r][c + qc + 4],     ah[mt][2], al[mt][2]);
                split_tf32(As[r + 8][c + qc + 4], ah[mt][3], al[mt][3]);
            }
            uint32_t bh[NT][2], bl[NT][2];
#pragma unroll
            for (int nt = 0; nt < NT; nt++) {
                int nn = warp_n * (NT * 8) + nt * 8 + qr;
                split_tf32(Bs[c + qc][nn],     bh[nt][0], bl[nt][0]);
                split_tf32(Bs[c + qc + 4][nn], bh[nt][1], bl[nt][1]);
            }
#pragma unroll
            for (int mt = 0; mt < 2; mt++)
#pragma unroll
                for (int nt = 0; nt < NT; nt++) {
                    // low-order terms first, then hi*hi
                    mma_tf32(acc[mt][nt], al[mt][0], al[mt][1], al[mt][2], al[mt][3],
                             bh[nt][0], bh[nt][1]);
                    mma_tf32(acc[mt][nt], ah[mt][0], ah[mt][1], ah[mt][2], ah[mt][3],
                             bl[nt][0], bl[nt][1]);
                    mma_tf32(acc[mt][nt], ah[mt][0], ah[mt][1], ah[mt][2], ah[mt][3],
                             bh[nt][0], bh[nt][1]);
                }
        }
        __syncthreads();
    }

    // --- epilogue: (c0,c1)/(c2,c3) are adjacent columns -> float2 stores ---
#pragma unroll
    for (int mt = 0; mt < 2; mt++) {
        int row = m0 + warp_m * 32 + mt * 16 + qr;
#pragma unroll
        for (int nt = 0; nt < NT; nt++) {
            int col = warp_n * (NT * 8) + nt * 8 + 2 * qc;
            if (row < M)
                *(float2*)(C + (size_t)row * BN + col) =
                    make_float2(acc[mt][nt].x, acc[mt][nt].y);
            if (row + 8 < M)
                *(float2*)(C + (size_t)(row + 8) * BN + col) =
                    make_float2(acc[mt][nt].z, acc[mt][nt].w);
        }
    }
}

// ---------------- gather aggregation, 128 feats: one warp per dst node --------
__global__ void __launch_bounds__(256) k_agg128(
    const int* __restrict__ start, const int* __restrict__ cnt,
    const int* __restrict__ csr, const float* __restrict__ dinv,
    const float* __restrict__ h, const float* __restrict__ bias,
    float* __restrict__ out, int n)
{
    int warp = (blockIdx.x * blockDim.x + threadIdx.x) >> 5;
    int lane = threadIdx.x & 31;
    if (warp >= n) return;
    const int d = warp;
    float dd = dinv[d];
    int beg = start[d];
    int num = cnt[d];

    float4 hv = *(const float4*)(h + (size_t)d * 128 + lane * 4);
    float4 bv = *(const float4*)(bias + lane * 4);
    float sd = dd * dd;
    float4 acc;
    acc.x = fmaf(sd, hv.x, bv.x); acc.y = fmaf(sd, hv.y, bv.y);
    acc.z = fmaf(sd, hv.z, bv.z); acc.w = fmaf(sd, hv.w, bv.w);

#pragma unroll 4
    for (int j = 0; j < num; j++) {
        int s = __ldg(&csr[beg + j]);
        float nrm = dd * __ldg(&dinv[s]);
        float4 v = __ldg((const float4*)(h + (size_t)s * 128) + lane);
        acc.x = fmaf(nrm, v.x, acc.x); acc.y = fmaf(nrm, v.y, acc.y);
        acc.z = fmaf(nrm, v.z, acc.z); acc.w = fmaf(nrm, v.w, acc.w);
    }
    *(float4*)(out + (size_t)d * 128 + lane * 4) = acc;
}

// ---------------- gather aggregation, 64 feats + fused final relu -------------
__global__ void __launch_bounds__(256) k_agg64_relu(
    const int* __restrict__ start, const int* __restrict__ cnt,
    const int* __restrict__ csr, const float* __restrict__ dinv,
    const float* __restrict__ h, const float* __restrict__ bias,
    float* __restrict__ out, int n)
{
    int warp = (blockIdx.x * blockDim.x + threadIdx.x) >> 5;
    int lane = threadIdx.x & 31;
    if (warp >= n) return;
    const int d = warp;
    float dd = dinv[d];
    int beg = start[d];
    int num = cnt[d];

    float2 hv = *(const float2*)(h + (size_t)d * 64 + lane * 2);
    float2 bv = *(const float2*)(bias + lane * 2);
    float sd = dd * dd;
    float2 acc;
    acc.x = fmaf(sd, hv.x, bv.x); acc.y = fmaf(sd, hv.y, bv.y);

#pragma unroll 4
    for (int j = 0; j < num; j++) {
        int s = __ldg(&csr[beg + j]);
        float nrm = dd * __ldg(&dinv[s]);
        float2 v = __ldg((const float2*)(h + (size_t)s * 64) + lane);
        acc.x = fmaf(nrm, v.x, acc.x); acc.y = fmaf(nrm, v.y, acc.y);
    }
    acc.x = fmaxf(acc.x, 0.f);
    acc.y = fmaxf(acc.y, 0.f);
    *(float2*)(out + (size_t)d * 64 + lane * 2) = acc;
}

// ==============================================================================
extern "C" void kernel_launch(void* const* d_in, const int* in_sizes, int n_in,
                              void* d_out, int out_size)
{
    const float* x    = (const float*)d_in[0];   // [N, 256]
    const int*   ei32 = (const int*)d_in[1];     // [2, E] int32 OR int64 (probed)
    const float* W1   = (const float*)d_in[2];   // [256, 128]
    const float* b1   = (const float*)d_in[3];   // [128]
    const float* W2   = (const float*)d_in[4];   // [128, 64]
    const float* b2   = (const float*)d_in[5];   // [64]
    float*       out  = (float*)d_out;           // [N, 64]

    const int n = in_sizes[0] / IN_CH;   // 50000
    const int e = in_sizes[1] / 2;       // 800000

    int *src, *dst, *cnt, *cursor, *startp, *incl, *bsum, *csr;
    float *dinv, *h1, *o1, *h2;
    cudaGetSymbolAddress((void**)&src,    g_src);
    cudaGetSymbolAddress((void**)&dst,    g_dst);
    cudaGetSymbolAddress((void**)&cnt,    g_cnt);
    cudaGetSymbolAddress((void**)&cursor, g_cursor);
    cudaGetSymbolAddress((void**)&startp, g_start);
    cudaGetSymbolAddress((void**)&incl,   g_incl);
    cudaGetSymbolAddress((void**)&bsum,   g_bsum);
    cudaGetSymbolAddress((void**)&csr,    g_csr_src);
    cudaGetSymbolAddress((void**)&dinv,   g_dinv);
    cudaGetSymbolAddress((void**)&h1,     g_h1);
    cudaGetSymbolAddress((void**)&o1,     g_o1);
    cudaGetSymbolAddress((void**)&h2,     g_h2);

    const int T = 256;
    const int nb = (n + T - 1) / T;
    const int eb = (e + T - 1) / T;

    // --- probe dtype, unpack edges, histogram (fused) ---
    k_reset<<<nb, T>>>(cnt, cursor, n);
    k_detect<<<4, T>>>(ei32, e);
    k_convert<<<eb, T>>>(ei32, src, dst, cnt, e);

    // --- CSR offsets + norms + fill ---
    k_scan_a<<<nb, T>>>(cnt, incl, bsum, n);
    k_scan_b<<<1, T>>>(bsum, nb);
    k_scan_c<<<nb, T>>>(cnt, incl, bsum, startp, dinv, n);
    k_fill<<<eb, T>>>(src, dst, startp, cursor, csr, e);

    // --- layer 1: h1 = x @ W1 (3xTF32 MMA); o1 = gcn_agg(h1) ---
    gemm_3xtf32<HID, false><<<(n + 127) / 128, 256>>>(x, W1, h1, n, IN_CH);
    k_agg128<<<(n * 32 + T - 1) / T, T>>>(startp, cnt, csr, dinv, h1, b1, o1, n);

    // --- layer 2: h2 = relu(o1) @ W2 (3xTF32 MMA); out = relu(gcn_agg(h2)) ---
    gemm_3xtf32<LAT, true><<<(n + 127) / 128, 256>>>(o1, W2, h2, n, HID);
    k_agg64_relu<<<(n * 32 + T - 1) / T, T>>>(startp, cnt, csr, dinv, h2, b2, out, n);
}

// round 8
// speedup vs baseline: 1.9177x; 1.1173x over previous
#include <cuda_runtime.h>
#include <cuda_bf16.h>
#include <cstdint>

#define NN 50000
#define EE 800000
#define IN_CH 256
#define HID 128
#define LAT 64
#define NB_SCAN ((NN + 255) / 256)   // 196

// ---------------- scratch (device globals; no allocation allowed) -------------
__device__ int   g_anynz;
__device__ int   g_cnt[NN];
__device__ int   g_cursor[NN];
__device__ int   g_start[NN];
__device__ int   g_incl[NN];
__device__ int   g_bsum[NB_SCAN];
__device__ int   g_csr_src[EE];
__device__ float g_dinv[NN];
__device__ float g_h1[(size_t)NN * HID];
__device__ float g_o1[(size_t)NN * HID];
__device__ float g_h2[(size_t)NN * LAT];

// ---------------- dtype probe ---------------------------------------------------
__global__ void k_reset(int* cnt, int n) {
    int i = blockIdx.x * blockDim.x + threadIdx.x;
    if (i == 0) g_anynz = 0;
    if (i < n) cnt[i] = 0;
}

// Sample odd int32 words: int64 layout => high words all zero; int32 => random.
__global__ void k_detect(const int* __restrict__ ei32, int e) {
    int t = threadIdx.x + blockIdx.x * blockDim.x;
    if (t >= 1024) return;
    long long k = (long long)t * (e / 1024);
    if (ei32[2 * k + 1] != 0) atomicOr(&g_anynz, 1);
}

// histogram straight from edge_index (no unpack pass)
__global__ void k_hist(const int* __restrict__ ei32, int* cnt, int e) {
    int i = blockIdx.x * blockDim.x + threadIdx.x;
    if (i >= e) return;
    int d = (g_anynz == 0) ? ei32[2 * ((size_t)e + i)] : ei32[e + i];
    atomicAdd(&cnt[d], 1);
}

// ---------------- CSR build ---------------------------------------------------
__global__ void k_scan_a(const int* __restrict__ cnt, int* incl, int* bsum, int n) {
    __shared__ int s[256];
    int i = blockIdx.x * 256 + threadIdx.x;
    int v = (i < n) ? cnt[i] : 0;
    s[threadIdx.x] = v;
    __syncthreads();
    for (int off = 1; off < 256; off <<= 1) {
        int t = (threadIdx.x >= off) ? s[threadIdx.x - off] : 0;
        __syncthreads();
        s[threadIdx.x] += t;
        __syncthreads();
    }
    if (i < n) incl[i] = s[threadIdx.x];
    if (threadIdx.x == 255) bsum[blockIdx.x] = s[255];
}

__global__ void k_scan_b(int* bsum, int nb) {
    __shared__ int s[256];
    int v = (threadIdx.x < nb) ? bsum[threadIdx.x] : 0;
    s[threadIdx.x] = v;
    __syncthreads();
    for (int off = 1; off < 256; off <<= 1) {
        int t = (threadIdx.x >= off) ? s[threadIdx.x - off] : 0;
        __syncthreads();
        s[threadIdx.x] += t;
        __syncthreads();
    }
    if (threadIdx.x < nb) bsum[threadIdx.x] = s[threadIdx.x];
}

// exclusive offsets into start AND cursor (fill consumes cursor), plus dinv
__global__ void k_scan_c(const int* __restrict__ cnt, const int* __restrict__ incl,
                         const int* __restrict__ bsum, int* start, int* cursor,
                         float* dinv, int n) {
    int i = blockIdx.x * 256 + threadIdx.x;
    if (i >= n) return;
    int bexcl = (blockIdx.x > 0) ? bsum[blockIdx.x - 1] : 0;
    int st = bexcl + incl[i] - cnt[i];
    start[i] = st;
    cursor[i] = st;
    dinv[i] = rsqrtf((float)(cnt[i] + 1));
}

// bucket fill straight from edge_index
__global__ void k_fill(const int* __restrict__ ei32, int* cursor, int* csr, int e) {
    int i = blockIdx.x * blockDim.x + threadIdx.x;
    if (i >= e) return;
    int s, d;
    if (g_anynz == 0) {            // int64 little-endian: low word carries index
        s = ei32[2 * (size_t)i];
        d = ei32[2 * ((size_t)e + i)];
    } else {                       // int32
        s = ei32[i];
        d = ei32[e + i];
    }
    int pos = atomicAdd(&cursor[d], 1);
    csr[pos] = s;
}

// ---------------- 3xTF32 tensor-core GEMM: C[M,BN] = op(A)[M,K] @ B[K,BN] -----
__device__ __forceinline__ void mma_tf32(float4& d,
                                         uint32_t a0, uint32_t a1, uint32_t a2, uint32_t a3,
                                         uint32_t b0, uint32_t b1) {
    asm volatile(
        "mma.sync.aligned.m16n8k8.row.col.f32.tf32.tf32.f32 "
        "{%0,%1,%2,%3}, {%4,%5,%6,%7}, {%8,%9}, {%0,%1,%2,%3};"
        : "+f"(d.x), "+f"(d.y), "+f"(d.z), "+f"(d.w)
        : "r"(a0), "r"(a1), "r"(a2), "r"(a3), "r"(b0), "r"(b1));
}

__device__ __forceinline__ void split_tf32(float f, uint32_t& hi, uint32_t& lo) {
    uint32_t h = __float_as_uint(f) & 0xFFFFE000u;   // exact truncation
    hi = h;
    lo = __float_as_uint(f - __uint_as_float(h));    // exact residual
}

template <int BN, bool RELU_A>
__global__ void __launch_bounds__(256) gemm_3xtf32(
    const float* __restrict__ A, const float* __restrict__ B,
    float* __restrict__ C, int M, int K)
{
    constexpr int BM = 128, BK = 32;
    constexpr int NT = BN / 16;            // n8 tiles per warp (8 or 4)
    __shared__ float As[BM][BK + 4];       // [m][k], pad 4
    __shared__ float Bs[BK][BN + 8];       // [k][n], pad 8

    const int tid    = threadIdx.x;
    const int warp   = tid >> 5;
    const int lane   = tid & 31;
    const int warp_m = warp & 3;
    const int warp_n = warp >> 2;
    const int m0     = blockIdx.x * BM;
    const int qr     = lane >> 2;          // 0..7
    const int qc     = lane & 3;           // 0..3

    float4 acc[2][NT];
#pragma unroll
    for (int i = 0; i < 2; i++)
#pragma unroll
        for (int j = 0; j < NT; j++) acc[i][j] = make_float4(0.f, 0.f, 0.f, 0.f);

    for (int k0 = 0; k0 < K; k0 += BK) {
        // --- A tile: 128x32 = 1024 float4, 4 per thread, coalesced ---
#pragma unroll
        for (int i = 0; i < 4; i++) {
            int idx = tid + i * 256;
            int m   = idx >> 3;
            int k4  = (idx & 7) << 2;
            float4 v = make_float4(0.f, 0.f, 0.f, 0.f);
            if (m0 + m < M)
                v = *(const float4*)(A + (size_t)(m0 + m) * K + k0 + k4);
            if (RELU_A) {
                v.x = fmaxf(v.x, 0.f); v.y = fmaxf(v.y, 0.f);
                v.z = fmaxf(v.z, 0.f); v.w = fmaxf(v.w, 0.f);
            }
            *(float4*)&As[m][k4] = v;
        }
        // --- B tile: 32xBN, BN/32 float4 per thread ---
#pragma unroll
        for (int i = 0; i < BN / 32; i++) {
            int idx = tid + i * 256;
            int k   = idx / (BN / 4);
            int n4  = (idx % (BN / 4)) << 2;
            *(float4*)&Bs[k][n4] = *(const float4*)(B + (size_t)(k0 + k) * BN + n4);
        }
        __syncthreads();

#pragma unroll
        for (int ks = 0; ks < 4; ks++) {
            const int c = ks * 8;
            uint32_t ah[2][4], al[2][4];
#pragma unroll
            for (int mt = 0; mt < 2; mt++) {
                int r = warp_m * 32 + mt * 16 + qr;
                split_tf32(As[r][c + qc],         ah[mt][0], al[mt][0]);
                split_tf32(As[r + 8][c + qc],     ah[mt][1], al[mt][1]);
                split_tf32(As[r][c + qc + 4],     ah[mt][2], al[mt][2]);
                split_tf32(As[r + 8][c + qc + 4], ah[mt][3], al[mt][3]);
            }
            uint32_t bh[NT][2], bl[NT][2];
#pragma unroll
            for (int nt = 0; nt < NT; nt++) {
                int nn = warp_n * (NT * 8) + nt * 8 + qr;
                split_tf32(Bs[c + qc][nn],     bh[nt][0], bl[nt][0]);
                split_tf32(Bs[c + qc + 4][nn], bh[nt][1], bl[nt][1]);
            }
#pragma unroll
            for (int mt = 0; mt < 2; mt++)
#pragma unroll
                for (int nt = 0; nt < NT; nt++) {
                    mma_tf32(acc[mt][nt], al[mt][0], al[mt][1], al[mt][2], al[mt][3],
                             bh[nt][0], bh[nt][1]);
                    mma_tf32(acc[mt][nt], ah[mt][0], ah[mt][1], ah[mt][2], ah[mt][3],
                             bl[nt][0], bl[nt][1]);
                    mma_tf32(acc[mt][nt], ah[mt][0], ah[mt][1], ah[mt][2], ah[mt][3],
                             bh[nt][0], bh[nt][1]);
                }
        }
        __syncthreads();
    }

#pragma unroll
    for (int mt = 0; mt < 2; mt++) {
        int row = m0 + warp_m * 32 + mt * 16 + qr;
#pragma unroll
        for (int nt = 0; nt < NT; nt++) {
            int col = warp_n * (NT * 8) + nt * 8 + 2 * qc;
            if (row < M)
                *(float2*)(C + (size_t)row * BN + col) =
                    make_float2(acc[mt][nt].x, acc[mt][nt].y);
            if (row + 8 < M)
                *(float2*)(C + (size_t)(row + 8) * BN + col) =
                    make_float2(acc[mt][nt].z, acc[mt][nt].w);
        }
    }
}

// ---------------- gather aggregation, 128 feats: one warp per dst node --------
__global__ void __launch_bounds__(256) k_agg128(
    const int* __restrict__ start, const int* __restrict__ cnt,
    const int* __restrict__ csr, const float* __restrict__ dinv,
    const float* __restrict__ h, const float* __restrict__ bias,
    float* __restrict__ out, int n)
{
    int warp = (blockIdx.x * blockDim.x + threadIdx.x) >> 5;
    int lane = threadIdx.x & 31;
    if (warp >= n) return;
    const int d = warp;
    float dd = dinv[d];
    int beg = start[d];
    int num = cnt[d];

    float4 hv = *(const float4*)(h + (size_t)d * 128 + lane * 4);
    float4 bv = *(const float4*)(bias + lane * 4);
    float sd = dd * dd;
    float4 acc;
    acc.x = fmaf(sd, hv.x, bv.x); acc.y = fmaf(sd, hv.y, bv.y);
    acc.z = fmaf(sd, hv.z, bv.z); acc.w = fmaf(sd, hv.w, bv.w);

#pragma unroll 4
    for (int j = 0; j < num; j++) {
        int s = __ldg(&csr[beg + j]);
        float nrm = dd * __ldg(&dinv[s]);
        float4 v = __ldg((const float4*)(h + (size_t)s * 128) + lane);
        acc.x = fmaf(nrm, v.x, acc.x); acc.y = fmaf(nrm, v.y, acc.y);
        acc.z = fmaf(nrm, v.z, acc.z); acc.w = fmaf(nrm, v.w, acc.w);
    }
    *(float4*)(out + (size_t)d * 128 + lane * 4) = acc;
}

// ---------------- gather aggregation, 64 feats + fused final relu -------------
__global__ void __launch_bounds__(256) k_agg64_relu(
    const int* __restrict__ start, const int* __restrict__ cnt,
    const int* __restrict__ csr, const float* __restrict__ dinv,
    const float* __restrict__ h, const float* __restrict__ bias,
    float* __restrict__ out, int n)
{
    int warp = (blockIdx.x * blockDim.x + threadIdx.x) >> 5;
    int lane = threadIdx.x & 31;
    if (warp >= n) return;
    const int d = warp;
    float dd = dinv[d];
    int beg = start[d];
    int num = cnt[d];

    float2 hv = *(const float2*)(h + (size_t)d * 64 + lane * 2);
    float2 bv = *(const float2*)(bias + lane * 2);
    float sd = dd * dd;
    float2 acc;
    acc.x = fmaf(sd, hv.x, bv.x); acc.y = fmaf(sd, hv.y, bv.y);

#pragma unroll 4
    for (int j = 0; j < num; j++) {
        int s = __ldg(&csr[beg + j]);
        float nrm = dd * __ldg(&dinv[s]);
        float2 v = __ldg((const float2*)(h + (size_t)s * 64) + lane);
        acc.x = fmaf(nrm, v.x, acc.x); acc.y = fmaf(nrm, v.y, acc.y);
    }
    acc.x = fmaxf(acc.x, 0.f);
    acc.y = fmaxf(acc.y, 0.f);
    *(float2*)(out + (size_t)d * 64 + lane * 2) = acc;
}

// ==============================================================================
extern "C" void kernel_launch(void* const* d_in, const int* in_sizes, int n_in,
                              void* d_out, int out_size)
{
    const float* x    = (const float*)d_in[0];   // [N, 256]
    const int*   ei32 = (const int*)d_in[1];     // [2, E] int32 OR int64 (probed)
    const float* W1   = (const float*)d_in[2];   // [256, 128]
    const float* b1   = (const float*)d_in[3];   // [128]
    const float* W2   = (const float*)d_in[4];   // [128, 64]
    const float* b2   = (const float*)d_in[5];   // [64]
    float*       out  = (float*)d_out;           // [N, 64]

    const int n = in_sizes[0] / IN_CH;   // 50000
    const int e = in_sizes[1] / 2;       // 800000

    int *cnt, *cursor, *startp, *incl, *bsum, *csr;
    float *dinv, *h1, *o1, *h2;
    cudaGetSymbolAddress((void**)&cnt,    g_cnt);
    cudaGetSymbolAddress((void**)&cursor, g_cursor);
    cudaGetSymbolAddress((void**)&startp, g_start);
    cudaGetSymbolAddress((void**)&incl,   g_incl);
    cudaGetSymbolAddress((void**)&bsum,   g_bsum);
    cudaGetSymbolAddress((void**)&csr,    g_csr_src);
    cudaGetSymbolAddress((void**)&dinv,   g_dinv);
    cudaGetSymbolAddress((void**)&h1,     g_h1);
    cudaGetSymbolAddress((void**)&o1,     g_o1);
    cudaGetSymbolAddress((void**)&h2,     g_h2);

    // side stream + events, created once on the first (uncaptured) call
    static cudaStream_t s2 = nullptr;
    static cudaEvent_t  ev_fork = nullptr, ev_join = nullptr;
    if (s2 == nullptr) {
        cudaStreamCreateWithFlags(&s2, cudaStreamNonBlocking);
        cudaEventCreateWithFlags(&ev_fork, cudaEventDisableTiming);
        cudaEventCreateWithFlags(&ev_join, cudaEventDisableTiming);
    }

    const int T = 256;
    const int nb = (n + T - 1) / T;
    const int eb = (e + T - 1) / T;

    // ---- fork: CSR build chain on s2, concurrent with GEMM1 on stream 0 ----
    cudaEventRecord(ev_fork, 0);
    cudaStreamWaitEvent(s2, ev_fork, 0);

    k_reset <<<nb, T, 0, s2>>>(cnt, n);
    k_detect<<<4,  T, 0, s2>>>(ei32, e);
    k_hist  <<<eb, T, 0, s2>>>(ei32, cnt, e);
    k_scan_a<<<nb, T, 0, s2>>>(cnt, incl, bsum, n);
    k_scan_b<<<1,  T, 0, s2>>>(bsum, nb);
    k_scan_c<<<nb, T, 0, s2>>>(cnt, incl, bsum, startp, cursor, dinv, n);
    k_fill  <<<eb, T, 0, s2>>>(ei32, cursor, csr, e);
    cudaEventRecord(ev_join, s2);

    // GEMM1 on the main stream, overlapping the CSR build
    gemm_3xtf32<HID, false><<<(n + 127) / 128, 256>>>(x, W1, h1, n, IN_CH);

    // ---- join: agg needs both h1 (stream 0) and CSR (s2) ----
    cudaStreamWaitEvent(0, ev_join, 0);

    k_agg128<<<(n * 32 + T - 1) / T, T>>>(startp, cnt, csr, dinv, h1, b1, o1, n);
    gemm_3xtf32<LAT, true><<<(n + 127) / 128, 256>>>(o1, W2, h2, n, HID);
    k_agg64_relu<<<(n * 32 + T - 1) / T, T>>>(startp, cnt, csr, dinv, h2, b2, out, n);
}

// round 9
// speedup vs baseline: 2.0007x; 1.0432x over previous
#include <cuda_runtime.h>
#include <cuda_bf16.h>
#include <cstdint>

#define NN 50000
#define EE 800000
#define IN_CH 256
#define HID 128
#define LAT 64
#define NB_SCAN ((NN + 255) / 256)   // 196

// ---------------- scratch (device globals; no allocation allowed) -------------
__device__ int   g_anynz;
__device__ int   g_cnt[NN];
__device__ int   g_cursor[NN];
__device__ int   g_start[NN];
__device__ int   g_incl[NN];
__device__ int   g_bsum[NB_SCAN];
__device__ int   g_csr_src[EE];
__device__ float g_dinv[NN];
__device__ float g_h1[(size_t)NN * HID];
__device__ float g_o1[(size_t)NN * HID];
__device__ float g_h2[(size_t)NN * LAT];

// ---------------- reset + dtype probe (fused) ---------------------------------
// Sample odd int32 words: int64 layout => high words all zero; int32 => random.
__global__ void k_reset_detect(const int* __restrict__ ei32, int* cnt, int n, int e) {
    int i = blockIdx.x * blockDim.x + threadIdx.x;
    if (i == 0) g_anynz = 0;
    if (i < n) cnt[i] = 0;
    if (i < 1024) {
        long long k = (long long)i * (e / 1024);
        if (ei32[2 * k + 1] != 0) atomicOr(&g_anynz, 1);
    }
}

// histogram straight from edge_index (no unpack pass)
__global__ void k_hist(const int* __restrict__ ei32, int* cnt, int e) {
    int i = blockIdx.x * blockDim.x + threadIdx.x;
    if (i >= e) return;
    int d = (g_anynz == 0) ? ei32[2 * ((size_t)e + i)] : ei32[e + i];
    atomicAdd(&cnt[d], 1);
}

// ---------------- CSR build ---------------------------------------------------
__global__ void k_scan_a(const int* __restrict__ cnt, int* incl, int* bsum, int n) {
    __shared__ int s[256];
    int i = blockIdx.x * 256 + threadIdx.x;
    int v = (i < n) ? cnt[i] : 0;
    s[threadIdx.x] = v;
    __syncthreads();
    for (int off = 1; off < 256; off <<= 1) {
        int t = (threadIdx.x >= off) ? s[threadIdx.x - off] : 0;
        __syncthreads();
        s[threadIdx.x] += t;
        __syncthreads();
    }
    if (i < n) incl[i] = s[threadIdx.x];
    if (threadIdx.x == 255) bsum[blockIdx.x] = s[255];
}

__global__ void k_scan_b(int* bsum, int nb) {
    __shared__ int s[256];
    int v = (threadIdx.x < nb) ? bsum[threadIdx.x] : 0;
    s[threadIdx.x] = v;
    __syncthreads();
    for (int off = 1; off < 256; off <<= 1) {
        int t = (threadIdx.x >= off) ? s[threadIdx.x - off] : 0;
        __syncthreads();
        s[threadIdx.x] += t;
        __syncthreads();
    }
    if (threadIdx.x < nb) bsum[threadIdx.x] = s[threadIdx.x];
}

// exclusive offsets into start AND cursor (fill consumes cursor), plus dinv
__global__ void k_scan_c(const int* __restrict__ cnt, const int* __restrict__ incl,
                         const int* __restrict__ bsum, int* start, int* cursor,
                         float* dinv, int n) {
    int i = blockIdx.x * 256 + threadIdx.x;
    if (i >= n) return;
    int bexcl = (blockIdx.x > 0) ? bsum[blockIdx.x - 1] : 0;
    int st = bexcl + incl[i] - cnt[i];
    start[i] = st;
    cursor[i] = st;
    dinv[i] = rsqrtf((float)(cnt[i] + 1));
}

// bucket fill straight from edge_index
__global__ void k_fill(const int* __restrict__ ei32, int* cursor, int* csr, int e) {
    int i = blockIdx.x * blockDim.x + threadIdx.x;
    if (i >= e) return;
    int s, d;
    if (g_anynz == 0) {            // int64 little-endian: low word carries index
        s = ei32[2 * (size_t)i];
        d = ei32[2 * ((size_t)e + i)];
    } else {                       // int32
        s = ei32[i];
        d = ei32[e + i];
    }
    int pos = atomicAdd(&cursor[d], 1);
    csr[pos] = s;
}

// ---------------- 3xTF32 tensor-core GEMM: C[M,BN] = op(A)[M,K] @ B[K,BN] -----
// Row-range form: processes rows [m_lo, m_hi). blockIdx maps from m_lo.
__device__ __forceinline__ void mma_tf32(float4& d,
                                         uint32_t a0, uint32_t a1, uint32_t a2, uint32_t a3,
                                         uint32_t b0, uint32_t b1) {
    asm volatile(
        "mma.sync.aligned.m16n8k8.row.col.f32.tf32.tf32.f32 "
        "{%0,%1,%2,%3}, {%4,%5,%6,%7}, {%8,%9}, {%0,%1,%2,%3};"
        : "+f"(d.x), "+f"(d.y), "+f"(d.z), "+f"(d.w)
        : "r"(a0), "r"(a1), "r"(a2), "r"(a3), "r"(b0), "r"(b1));
}

__device__ __forceinline__ void split_tf32(float f, uint32_t& hi, uint32_t& lo) {
    uint32_t h = __float_as_uint(f) & 0xFFFFE000u;   // exact truncation
    hi = h;
    lo = __float_as_uint(f - __uint_as_float(h));    // exact residual
}

template <int BN, bool RELU_A>
__global__ void __launch_bounds__(256) gemm_3xtf32(
    const float* __restrict__ A, const float* __restrict__ B,
    float* __restrict__ C, int m_lo, int m_hi, int K)
{
    constexpr int BM = 128, BK = 32;
    constexpr int NT = BN / 16;            // n8 tiles per warp (8 or 4)
    __shared__ float As[BM][BK + 4];       // [m][k], pad 4
    __shared__ float Bs[BK][BN + 8];       // [k][n], pad 8

    const int tid    = threadIdx.x;
    const int warp   = tid >> 5;
    const int lane   = tid & 31;
    const int warp_m = warp & 3;
    const int warp_n = warp >> 2;
    const int m0     = m_lo + blockIdx.x * BM;
    const int qr     = lane >> 2;          // 0..7
    const int qc     = lane & 3;           // 0..3

    float4 acc[2][NT];
#pragma unroll
    for (int i = 0; i < 2; i++)
#pragma unroll
        for (int j = 0; j < NT; j++) acc[i][j] = make_float4(0.f, 0.f, 0.f, 0.f);

    for (int k0 = 0; k0 < K; k0 += BK) {
        // --- A tile: 128x32 = 1024 float4, 4 per thread, coalesced ---
#pragma unroll
        for (int i = 0; i < 4; i++) {
            int idx = tid + i * 256;
            int m   = idx >> 3;
            int k4  = (idx & 7) << 2;
            float4 v = make_float4(0.f, 0.f, 0.f, 0.f);
            if (m0 + m < m_hi)
                v = *(const float4*)(A + (size_t)(m0 + m) * K + k0 + k4);
            if (RELU_A) {
                v.x = fmaxf(v.x, 0.f); v.y = fmaxf(v.y, 0.f);
                v.z = fmaxf(v.z, 0.f); v.w = fmaxf(v.w, 0.f);
            }
            *(float4*)&As[m][k4] = v;
        }
        // --- B tile: 32xBN, BN/32 float4 per thread ---
#pragma unroll
        for (int i = 0; i < BN / 32; i++) {
            int idx = tid + i * 256;
            int k   = idx / (BN / 4);
            int n4  = (idx % (BN / 4)) << 2;
            *(float4*)&Bs[k][n4] = *(const float4*)(B + (size_t)(k0 + k) * BN + n4);
        }
        __syncthreads();

#pragma unroll
        for (int ks = 0; ks < 4; ks++) {
            const int c = ks * 8;
            uint32_t ah[2][4], al[2][4];
#pragma unroll
            for (int mt = 0; mt < 2; mt++) {
                int r = warp_m * 32 + mt * 16 + qr;
                split_tf32(As[r][c + qc],         ah[mt][0], al[mt][0]);
                split_tf32(As[r + 8][c + qc],     ah[mt][1], al[mt][1]);
                split_tf32(As[r][c + qc + 4],     ah[mt][2], al[mt][2]);
                split_tf32(As[r + 8][c + qc + 4], ah[mt][3], al[mt][3]);
            }
            uint32_t bh[NT][2], bl[NT][2];
#pragma unroll
            for (int nt = 0; nt < NT; nt++) {
                int nn = warp_n * (NT * 8) + nt * 8 + qr;
                split_tf32(Bs[c + qc][nn],     bh[nt][0], bl[nt][0]);
                split_tf32(Bs[c + qc + 4][nn], bh[nt][1], bl[nt][1]);
            }
#pragma unroll
            for (int mt = 0; mt < 2; mt++)
#pragma unroll
                for (int nt = 0; nt < NT; nt++) {
                    mma_tf32(acc[mt][nt], al[mt][0], al[mt][1], al[mt][2], al[mt][3],
                             bh[nt][0], bh[nt][1]);
                    mma_tf32(acc[mt][nt], ah[mt][0], ah[mt][1], ah[mt][2], ah[mt][3],
                             bl[nt][0], bl[nt][1]);
                    mma_tf32(acc[mt][nt], ah[mt][0], ah[mt][1], ah[mt][2], ah[mt][3],
                             bh[nt][0], bh[nt][1]);
                }
        }
        __syncthreads();
    }

#pragma unroll
    for (int mt = 0; mt < 2; mt++) {
        int row = m0 + warp_m * 32 + mt * 16 + qr;
#pragma unroll
        for (int nt = 0; nt < NT; nt++) {
            int col = warp_n * (NT * 8) + nt * 8 + 2 * qc;
            if (row < m_hi)
                *(float2*)(C + (size_t)row * BN + col) =
                    make_float2(acc[mt][nt].x, acc[mt][nt].y);
            if (row + 8 < m_hi)
                *(float2*)(C + (size_t)(row + 8) * BN + col) =
                    make_float2(acc[mt][nt].z, acc[mt][nt].w);
        }
    }
}

// ---------------- gather aggregation, 128 feats: one warp per dst node --------
// Node-range form: nodes [n_lo, n_hi).
__global__ void __launch_bounds__(256) k_agg128(
    const int* __restrict__ start, const int* __restrict__ cnt,
    const int* __restrict__ csr, const float* __restrict__ dinv,
    const float* __restrict__ h, const float* __restrict__ bias,
    float* __restrict__ out, int n_lo, int n_hi)
{
    int d = n_lo + ((blockIdx.x * blockDim.x + threadIdx.x) >> 5);
    int lane = threadIdx.x & 31;
    if (d >= n_hi) return;
    float dd = dinv[d];
    int beg = start[d];
    int num = cnt[d];

    float4 hv = *(const float4*)(h + (size_t)d * 128 + lane * 4);
    float4 bv = *(const float4*)(bias + lane * 4);
    float sd = dd * dd;
    float4 acc;
    acc.x = fmaf(sd, hv.x, bv.x); acc.y = fmaf(sd, hv.y, bv.y);
    acc.z = fmaf(sd, hv.z, bv.z); acc.w = fmaf(sd, hv.w, bv.w);

#pragma unroll 4
    for (int j = 0; j < num; j++) {
        int s = __ldg(&csr[beg + j]);
        float nrm = dd * __ldg(&dinv[s]);
        float4 v = __ldg((const float4*)(h + (size_t)s * 128) + lane);
        acc.x = fmaf(nrm, v.x, acc.x); acc.y = fmaf(nrm, v.y, acc.y);
        acc.z = fmaf(nrm, v.z, acc.z); acc.w = fmaf(nrm, v.w, acc.w);
    }
    *(float4*)(out + (size_t)d * 128 + lane * 4) = acc;
}

// ---------------- gather aggregation, 64 feats + fused final relu -------------
__global__ void __launch_bounds__(256) k_agg64_relu(
    const int* __restrict__ start, const int* __restrict__ cnt,
    const int* __restrict__ csr, const float* __restrict__ dinv,
    const float* __restrict__ h, const float* __restrict__ bias,
    float* __restrict__ out, int n)
{
    int d = (blockIdx.x * blockDim.x + threadIdx.x) >> 5;
    int lane = threadIdx.x & 31;
    if (d >= n) return;
    float dd = dinv[d];
    int beg = start[d];
    int num = cnt[d];

    float2 hv = *(const float2*)(h + (size_t)d * 64 + lane * 2);
    float2 bv = *(const float2*)(bias + lane * 2);
    float sd = dd * dd;
    float2 acc;
    acc.x = fmaf(sd, hv.x, bv.x); acc.y = fmaf(sd, hv.y, bv.y);

#pragma unroll 4
    for (int j = 0; j < num; j++) {
        int s = __ldg(&csr[beg + j]);
        float nrm = dd * __ldg(&dinv[s]);
        float2 v = __ldg((const float2*)(h + (size_t)s * 64) + lane);
        acc.x = fmaf(nrm, v.x, acc.x); acc.y = fmaf(nrm, v.y, acc.y);
    }
    acc.x = fmaxf(acc.x, 0.f);
    acc.y = fmaxf(acc.y, 0.f);
    *(float2*)(out + (size_t)d * 64 + lane * 2) = acc;
}

// ==============================================================================
extern "C" void kernel_launch(void* const* d_in, const int* in_sizes, int n_in,
                              void* d_out, int out_size)
{
    const float* x    = (const float*)d_in[0];   // [N, 256]
    const int*   ei32 = (const int*)d_in[1];     // [2, E] int32 OR int64 (probed)
    const float* W1   = (const float*)d_in[2];   // [256, 128]
    const float* b1   = (const float*)d_in[3];   // [128]
    const float* W2   = (const float*)d_in[4];   // [128, 64]
    const float* b2   = (const float*)d_in[5];   // [64]
    float*       out  = (float*)d_out;           // [N, 64]

    const int n = in_sizes[0] / IN_CH;   // 50000
    const int e = in_sizes[1] / 2;       // 800000

    int *cnt, *cursor, *startp, *incl, *bsum, *csr;
    float *dinv, *h1, *o1, *h2;
    cudaGetSymbolAddress((void**)&cnt,    g_cnt);
    cudaGetSymbolAddress((void**)&cursor, g_cursor);
    cudaGetSymbolAddress((void**)&startp, g_start);
    cudaGetSymbolAddress((void**)&incl,   g_incl);
    cudaGetSymbolAddress((void**)&bsum,   g_bsum);
    cudaGetSymbolAddress((void**)&csr,    g_csr_src);
    cudaGetSymbolAddress((void**)&dinv,   g_dinv);
    cudaGetSymbolAddress((void**)&h1,     g_h1);
    cudaGetSymbolAddress((void**)&o1,     g_o1);
    cudaGetSymbolAddress((void**)&h2,     g_h2);

    // side stream + events, created once on the first (uncaptured) call
    static cudaStream_t s2 = nullptr;
    static cudaEvent_t  ev_fork = nullptr, ev_csr = nullptr,
                        ev_g1 = nullptr, ev_c1 = nullptr;
    if (s2 == nullptr) {
        cudaStreamCreateWithFlags(&s2, cudaStreamNonBlocking);
        cudaEventCreateWithFlags(&ev_fork, cudaEventDisableTiming);
        cudaEventCreateWithFlags(&ev_csr,  cudaEventDisableTiming);
        cudaEventCreateWithFlags(&ev_g1,   cudaEventDisableTiming);
        cudaEventCreateWithFlags(&ev_c1,   cudaEventDisableTiming);
    }

    const int T = 256;
    const int nb = (n + T - 1) / T;
    const int eb = (e + T - 1) / T;

    const int half = ((n / 2) + 127) & ~127;     // chunk boundary, 128-aligned

    // ---- fork: CSR build chain on s2, concurrent with GEMM1 on stream 0 ----
    cudaEventRecord(ev_fork, 0);
    cudaStreamWaitEvent(s2, ev_fork, 0);

    k_reset_detect<<<nb, T, 0, s2>>>(ei32, cnt, n, e);
    k_hist  <<<eb, T, 0, s2>>>(ei32, cnt, e);
    k_scan_a<<<nb, T, 0, s2>>>(cnt, incl, bsum, n);
    k_scan_b<<<1,  T, 0, s2>>>(bsum, nb);
    k_scan_c<<<nb, T, 0, s2>>>(cnt, incl, bsum, startp, cursor, dinv, n);
    k_fill  <<<eb, T, 0, s2>>>(ei32, cursor, csr, e);
    cudaEventRecord(ev_csr, s2);

    // GEMM1 on the main stream, overlapping the CSR build
    gemm_3xtf32<HID, false><<<(n + 127) / 128, 256>>>(x, W1, h1, 0, n, IN_CH);
    cudaEventRecord(ev_g1, 0);

    // ---- chunked layer-1 agg + layer-2 GEMM, two independent chains --------
    // chain 0 (stream 0): nodes [0, half)   — needs CSR from s2
    cudaStreamWaitEvent(0, ev_csr, 0);
    k_agg128<<<(half * 32 + T - 1) / T, T>>>(startp, cnt, csr, dinv, h1, b1, o1, 0, half);
    gemm_3xtf32<LAT, true><<<half / 128, 256>>>(o1, W2, h2, 0, half, HID);

    // chain 1 (stream s2): nodes [half, n)  — needs h1 from stream 0
    cudaStreamWaitEvent(s2, ev_g1, 0);
    k_agg128<<<((n - half) * 32 + T - 1) / T, T, 0, s2>>>(startp, cnt, csr, dinv, h1, b1, o1, half, n);
    gemm_3xtf32<LAT, true><<<(n - half + 127) / 128, 256, 0, s2>>>(o1, W2, h2, half, n, HID);
    cudaEventRecord(ev_c1, s2);

    // ---- join: agg64 needs the full h2 ----
    cudaStreamWaitEvent(0, ev_c1, 0);
    k_agg64_relu<<<(n * 32 + T - 1) / T, T>>>(startp, cnt, csr, dinv, h2, b2, out, n);
}

// round 10
// speedup vs baseline: 2.0178x; 1.0085x over previous
#include <cuda_runtime.h>
#include <cuda_bf16.h>
#include <cstdint>

#define NN 50000
#define EE 800000
#define IN_CH 256
#define HID 128
#define LAT 64
#define NB_SCAN ((NN + 255) / 256)   // 196

// ---------------- scratch (device globals; no allocation allowed) -------------
__device__ int      g_anynz;
__device__ int      g_cnt[NN];
__device__ int      g_cursor[NN];
__device__ int      g_start[NN];
__device__ unsigned g_scan_pack[NB_SCAN];  // bits31-30: 0=none,1=agg,2=incl; bits29-0: value
__device__ unsigned g_scan_ctr;
__device__ int      g_csr_src[EE];
__device__ float    g_dinv[NN];
__device__ float    g_h1[(size_t)NN * HID];
__device__ float    g_o1[(size_t)NN * HID];
__device__ float    g_h2[(size_t)NN * LAT];

// ---------------- reset + dtype probe (fused) ---------------------------------
// Sample odd int32 words: int64 layout => high words all zero; int32 => random.
__global__ void k_reset_detect(const int* __restrict__ ei32, int* cnt, int n, int e,
                               int nblk) {
    int i = blockIdx.x * blockDim.x + threadIdx.x;
    if (i == 0) { g_anynz = 0; g_scan_ctr = 0; }
    if (i < n) cnt[i] = 0;
    if (i < nblk) g_scan_pack[i] = 0;
    if (i < 1024) {
        long long k = (long long)i * (e / 1024);
        if (ei32[2 * k + 1] != 0) atomicOr(&g_anynz, 1);
    }
}

// histogram straight from edge_index (no unpack pass)
__global__ void k_hist(const int* __restrict__ ei32, int* cnt, int e) {
    int i = blockIdx.x * blockDim.x + threadIdx.x;
    if (i >= e) return;
    int d = (g_anynz == 0) ? ei32[2 * ((size_t)e + i)] : ei32[e + i];
    atomicAdd(&cnt[d], 1);
}

// ---------------- single-pass decoupled-lookback scan --------------------------
// Replaces scan_a/b/c: exclusive offsets -> start & cursor, plus dinv.
__global__ void __launch_bounds__(256) k_scan_lookback(
    const int* __restrict__ cnt, int* start, int* cursor, float* dinv, int n)
{
    __shared__ int s[256];
    __shared__ int sbid;
    __shared__ int sprefix;
    const int tid = threadIdx.x;
    if (tid == 0) sbid = (int)atomicAdd(&g_scan_ctr, 1u);   // ticket order
    __syncthreads();
    const int bid = sbid;
    const int i = bid * 256 + tid;
    const int v = (i < n) ? cnt[i] : 0;

    // block-wide inclusive scan in smem
    s[tid] = v;
    __syncthreads();
    for (int off = 1; off < 256; off <<= 1) {
        int t = (tid >= off) ? s[tid - off] : 0;
        __syncthreads();
        s[tid] += t;
        __syncthreads();
    }
    const int total = s[255];

    // publish aggregate (block 0 publishes inclusive immediately)
    if (tid == 0) {
        unsigned st = (bid == 0) ? 2u : 1u;
        atomicExch(&g_scan_pack[bid], (st << 30) | (unsigned)total);
    }

    // warp 0: lookback over predecessors
    if (tid < 32) {
        int prefix = 0;
        if (bid > 0) {
            int j = bid - 1;
            bool done = false;
            while (!done) {
                int idx = j - tid;
                unsigned p;
                if (idx >= 0) {
                    do { p = *(volatile unsigned*)&g_scan_pack[idx]; } while ((p >> 30) == 0u);
                } else {
                    p = (2u << 30);            // virtual inclusive 0 before block 0
                }
                unsigned stt = p >> 30;
                int val = (int)(p & 0x3FFFFFFFu);
                unsigned incl_mask = __ballot_sync(0xFFFFFFFFu, stt == 2u);
                int firstIncl = __ffs(incl_mask) - 1;   // closest inclusive predecessor
                int contrib;
                if (firstIncl >= 0) {
                    contrib = (tid <= firstIncl) ? val : 0;
                    done = true;
                } else {
                    contrib = (idx >= 0) ? val : 0;
                    j -= 32;
                }
#pragma unroll
                for (int o = 16; o; o >>= 1) contrib += __shfl_down_sync(0xFFFFFFFFu, contrib, o);
                prefix += __shfl_sync(0xFFFFFFFFu, contrib, 0);
            }
        }
        if (tid == 0) {
            sprefix = prefix;
            if (bid > 0)
                atomicExch(&g_scan_pack[bid], (2u << 30) | (unsigned)(prefix + total));
        }
    }
    __syncthreads();

    if (i < n) {
        int st = sprefix + s[tid] - v;      // exclusive offset
        start[i] = st;
        cursor[i] = st;
        dinv[i] = rsqrtf((float)(v + 1));
    }
}

// bucket fill straight from edge_index
__global__ void k_fill(const int* __restrict__ ei32, int* cursor, int* csr, int e) {
    int i = blockIdx.x * blockDim.x + threadIdx.x;
    if (i >= e) return;
    int s, d;
    if (g_anynz == 0) {            // int64 little-endian: low word carries index
        s = ei32[2 * (size_t)i];
        d = ei32[2 * ((size_t)e + i)];
    } else {                       // int32
        s = ei32[i];
        d = ei32[e + i];
    }
    int pos = atomicAdd(&cursor[d], 1);
    csr[pos] = s;
}

// ---------------- 3xTF32 tensor-core GEMM, register-prefetch pipelined --------
__device__ __forceinline__ void mma_tf32(float4& d,
                                         uint32_t a0, uint32_t a1, uint32_t a2, uint32_t a3,
                                         uint32_t b0, uint32_t b1) {
    asm volatile(
        "mma.sync.aligned.m16n8k8.row.col.f32.tf32.tf32.f32 "
        "{%0,%1,%2,%3}, {%4,%5,%6,%7}, {%8,%9}, {%0,%1,%2,%3};"
        : "+f"(d.x), "+f"(d.y), "+f"(d.z), "+f"(d.w)
        : "r"(a0), "r"(a1), "r"(a2), "r"(a3), "r"(b0), "r"(b1));
}

__device__ __forceinline__ void split_tf32(float f, uint32_t& hi, uint32_t& lo) {
    uint32_t h = __float_as_uint(f) & 0xFFFFE000u;   // exact truncation
    hi = h;
    lo = __float_as_uint(f - __uint_as_float(h));    // exact residual
}

template <int BN, bool RELU_A>
__global__ void __launch_bounds__(256) gemm_3xtf32(
    const float* __restrict__ A, const float* __restrict__ B,
    float* __restrict__ C, int m_lo, int m_hi, int K)
{
    constexpr int BM = 128, BK = 32;
    constexpr int NT = BN / 16;            // n8 tiles per warp (8 or 4)
    constexpr int NBV = BN / 32;           // B float4 loads per thread
    __shared__ float As[BM][BK + 4];       // [m][k], pad 4
    __shared__ float Bs[BK][BN + 8];       // [k][n], pad 8

    const int tid    = threadIdx.x;
    const int warp   = tid >> 5;
    const int lane   = tid & 31;
    const int warp_m = warp & 3;
    const int warp_n = warp >> 2;
    const int m0     = m_lo + blockIdx.x * BM;
    const int qr     = lane >> 2;          // 0..7
    const int qc     = lane & 3;           // 0..3

    // per-thread tile-load coordinates
    const int am  = tid >> 3;              // A row     (with +256 stride -> 4 rows)
    const int ak4 = (tid & 7) << 2;        // A k offset
    const int bk  = tid / (BN / 4);        // B k row   (with stride)
    const int bn4 = (tid % (BN / 4)) << 2; // B n offset
    const int bkStride = 256 / (BN / 4);

    float4 acc[2][NT];
#pragma unroll
    for (int i = 0; i < 2; i++)
#pragma unroll
        for (int j = 0; j < NT; j++) acc[i][j] = make_float4(0.f, 0.f, 0.f, 0.f);

    // ---- load tile 0 into smem ----
#pragma unroll
    for (int i = 0; i < 4; i++) {
        int m = am + i * 32;
        float4 v = make_float4(0.f, 0.f, 0.f, 0.f);
        if (m0 + m < m_hi)
            v = *(const float4*)(A + (size_t)(m0 + m) * K + ak4);
        if (RELU_A) {
            v.x = fmaxf(v.x, 0.f); v.y = fmaxf(v.y, 0.f);
            v.z = fmaxf(v.z, 0.f); v.w = fmaxf(v.w, 0.f);
        }
        *(float4*)&As[m][ak4] = v;
    }
#pragma unroll
    for (int i = 0; i < NBV; i++) {
        int k = bk + i * bkStride;
        *(float4*)&Bs[k][bn4] = *(const float4*)(B + (size_t)k * BN + bn4);
    }
    __syncthreads();

    for (int k0 = 0; k0 < K; k0 += BK) {
        // ---- prefetch next tile into registers (GMEM latency hidden by MMAs) ----
        const bool has_next = (k0 + BK < K);
        float4 pa[4], pb[NBV];
        if (has_next) {
#pragma unroll
            for (int i = 0; i < 4; i++) {
                int m = am + i * 32;
                float4 v = make_float4(0.f, 0.f, 0.f, 0.f);
                if (m0 + m < m_hi)
                    v = *(const float4*)(A + (size_t)(m0 + m) * K + (k0 + BK) + ak4);
                if (RELU_A) {
                    v.x = fmaxf(v.x, 0.f); v.y = fmaxf(v.y, 0.f);
                    v.z = fmaxf(v.z, 0.f); v.w = fmaxf(v.w, 0.f);
                }
                pa[i] = v;
            }
#pragma unroll
            for (int i = 0; i < NBV; i++) {
                int k = bk + i * bkStride;
                pb[i] = *(const float4*)(B + (size_t)(k0 + BK + k) * BN + bn4);
            }
        }

        // ---- compute on current smem tile ----
#pragma unroll
        for (int ks = 0; ks < 4; ks++) {
            const int c = ks * 8;
            uint32_t ah[2][4], al[2][4];
#pragma unroll
            for (int mt = 0; mt < 2; mt++) {
                int r = warp_m * 32 + mt * 16 + qr;
                split_tf32(As[r][c + qc],         ah[mt][0], al[mt][0]);
                split_tf32(As[r + 8][c + qc],     ah[mt][1], al[mt][1]);
                split_tf32(As[r][c + qc + 4],     ah[mt][2], al[mt][2]);
                split_tf32(As[r + 8][c + qc + 4], ah[mt][3], al[mt][3]);
            }
            uint32_t bh[NT][2], bl[NT][2];
#pragma unroll
            for (int nt = 0; nt < NT; nt++) {
                int nn = warp_n * (NT * 8) + nt * 8 + qr;
                split_tf32(Bs[c + qc][nn],     bh[nt][0], bl[nt][0]);
                split_tf32(Bs[c + qc + 4][nn], bh[nt][1], bl[nt][1]);
            }
#pragma unroll
            for (int mt = 0; mt < 2; mt++)
#pragma unroll
                for (int nt = 0; nt < NT; nt++) {
                    mma_tf32(acc[mt][nt], al[mt][0], al[mt][1], al[mt][2], al[mt][3],
                             bh[nt][0], bh[nt][1]);
                    mma_tf32(acc[mt][nt], ah[mt][0], ah[mt][1], ah[mt][2], ah[mt][3],
                             bl[nt][0], bl[nt][1]);
                    mma_tf32(acc[mt][nt], ah[mt][0], ah[mt][1], ah[mt][2], ah[mt][3],
                             bh[nt][0], bh[nt][1]);
                }
        }
        __syncthreads();

        // ---- commit prefetched tile ----
        if (has_next) {
#pragma unroll
            for (int i = 0; i < 4; i++)
                *(float4*)&As[am + i * 32][ak4] = pa[i];
#pragma unroll
            for (int i = 0; i < NBV; i++)
                *(float4*)&Bs[bk + i * bkStride][bn4] = pb[i];
            __syncthreads();
        }
    }

#pragma unroll
    for (int mt = 0; mt < 2; mt++) {
        int row = m0 + warp_m * 32 + mt * 16 + qr;
#pragma unroll
        for (int nt = 0; nt < NT; nt++) {
            int col = warp_n * (NT * 8) + nt * 8 + 2 * qc;
            if (row < m_hi)
                *(float2*)(C + (size_t)row * BN + col) =
                    make_float2(acc[mt][nt].x, acc[mt][nt].y);
            if (row + 8 < m_hi)
                *(float2*)(C + (size_t)(row + 8) * BN + col) =
                    make_float2(acc[mt][nt].z, acc[mt][nt].w);
        }
    }
}

// ---------------- gather aggregation, 128 feats: one warp per dst node --------
__global__ void __launch_bounds__(256) k_agg128(
    const int* __restrict__ start, const int* __restrict__ cnt,
    const int* __restrict__ csr, const float* __restrict__ dinv,
    const float* __restrict__ h, const float* __restrict__ bias,
    float* __restrict__ out, int n_lo, int n_hi)
{
    int d = n_lo + ((blockIdx.x * blockDim.x + threadIdx.x) >> 5);
    int lane = threadIdx.x & 31;
    if (d >= n_hi) return;
    float dd = dinv[d];
    int beg = start[d];
    int num = cnt[d];

    float4 hv = *(const float4*)(h + (size_t)d * 128 + lane * 4);
    float4 bv = *(const float4*)(bias + lane * 4);
    float sd = dd * dd;
    float4 acc;
    acc.x = fmaf(sd, hv.x, bv.x); acc.y = fmaf(sd, hv.y, bv.y);
    acc.z = fmaf(sd, hv.z, bv.z); acc.w = fmaf(sd, hv.w, bv.w);

#pragma unroll 4
    for (int j = 0; j < num; j++) {
        int s = __ldg(&csr[beg + j]);
        float nrm = dd * __ldg(&dinv[s]);
        float4 v = __ldg((const float4*)(h + (size_t)s * 128) + lane);
        acc.x = fmaf(nrm, v.x, acc.x); acc.y = fmaf(nrm, v.y, acc.y);
        acc.z = fmaf(nrm, v.z, acc.z); acc.w = fmaf(nrm, v.w, acc.w);
    }
    *(float4*)(out + (size_t)d * 128 + lane * 4) = acc;
}

// ---------------- gather aggregation, 64 feats + fused final relu -------------
__global__ void __launch_bounds__(256) k_agg64_relu(
    const int* __restrict__ start, const int* __restrict__ cnt,
    const int* __restrict__ csr, const float* __restrict__ dinv,
    const float* __restrict__ h, const float* __restrict__ bias,
    float* __restrict__ out, int n)
{
    int d = (blockIdx.x * blockDim.x + threadIdx.x) >> 5;
    int lane = threadIdx.x & 31;
    if (d >= n) return;
    float dd = dinv[d];
    int beg = start[d];
    int num = cnt[d];

    float2 hv = *(const float2*)(h + (size_t)d * 64 + lane * 2);
    float2 bv = *(const float2*)(bias + lane * 2);
    float sd = dd * dd;
    float2 acc;
    acc.x = fmaf(sd, hv.x, bv.x); acc.y = fmaf(sd, hv.y, bv.y);

#pragma unroll 4
    for (int j = 0; j < num; j++) {
        int s = __ldg(&csr[beg + j]);
        float nrm = dd * __ldg(&dinv[s]);
        float2 v = __ldg((const float2*)(h + (size_t)s * 64) + lane);
        acc.x = fmaf(nrm, v.x, acc.x); acc.y = fmaf(nrm, v.y, acc.y);
    }
    acc.x = fmaxf(acc.x, 0.f);
    acc.y = fmaxf(acc.y, 0.f);
    *(float2*)(out + (size_t)d * 64 + lane * 2) = acc;
}

// ==============================================================================
extern "C" void kernel_launch(void* const* d_in, const int* in_sizes, int n_in,
                              void* d_out, int out_size)
{
    const float* x    = (const float*)d_in[0];   // [N, 256]
    const int*   ei32 = (const int*)d_in[1];     // [2, E] int32 OR int64 (probed)
    const float* W1   = (const float*)d_in[2];   // [256, 128]
    const float* b1   = (const float*)d_in[3];   // [128]
    const float* W2   = (const float*)d_in[4];   // [128, 64]
    const float* b2   = (const float*)d_in[5];   // [64]
    float*       out  = (float*)d_out;           // [N, 64]

    const int n = in_sizes[0] / IN_CH;   // 50000
    const int e = in_sizes[1] / 2;       // 800000

    int *cnt, *cursor, *startp, *csr;
    float *dinv, *h1, *o1, *h2;
    cudaGetSymbolAddress((void**)&cnt,    g_cnt);
    cudaGetSymbolAddress((void**)&cursor, g_cursor);
    cudaGetSymbolAddress((void**)&startp, g_start);
    cudaGetSymbolAddress((void**)&csr,    g_csr_src);
    cudaGetSymbolAddress((void**)&dinv,   g_dinv);
    cudaGetSymbolAddress((void**)&h1,     g_h1);
    cudaGetSymbolAddress((void**)&o1,     g_o1);
    cudaGetSymbolAddress((void**)&h2,     g_h2);

    // side stream + events, created once on the first (uncaptured) call
    static cudaStream_t s2 = nullptr;
    static cudaEvent_t  ev_fork = nullptr, ev_csr = nullptr,
                        ev_g1 = nullptr, ev_c1 = nullptr;
    if (s2 == nullptr) {
        cudaStreamCreateWithFlags(&s2, cudaStreamNonBlocking);
        cudaEventCreateWithFlags(&ev_fork, cudaEventDisableTiming);
        cudaEventCreateWithFlags(&ev_csr,  cudaEventDisableTiming);
        cudaEventCreateWithFlags(&ev_g1,   cudaEventDisableTiming);
        cudaEventCreateWithFlags(&ev_c1,   cudaEventDisableTiming);
    }

    const int T = 256;
    const int nb = (n + T - 1) / T;
    const int eb = (e + T - 1) / T;
    const int half = ((n / 2) + 127) & ~127;     // chunk boundary, 128-aligned

    // ---- fork: CSR build chain on s2, concurrent with GEMM1 on stream 0 ----
    cudaEventRecord(ev_fork, 0);
    cudaStreamWaitEvent(s2, ev_fork, 0);

    k_reset_detect <<<nb, T, 0, s2>>>(ei32, cnt, n, e, nb);
    k_hist         <<<eb, T, 0, s2>>>(ei32, cnt, e);
    k_scan_lookback<<<nb, T, 0, s2>>>(cnt, startp, cursor, dinv, n);
    k_fill         <<<eb, T, 0, s2>>>(ei32, cursor, csr, e);
    cudaEventRecord(ev_csr, s2);

    // GEMM1 on the main stream, overlapping the CSR build
    gemm_3xtf32<HID, false><<<(n + 127) / 128, 256>>>(x, W1, h1, 0, n, IN_CH);
    cudaEventRecord(ev_g1, 0);

    // ---- chunked layer-1 agg + layer-2 GEMM, two independent chains --------
    // chain 0 (stream 0): nodes [0, half)   — needs CSR from s2
    cudaStreamWaitEvent(0, ev_csr, 0);
    k_agg128<<<(half * 32 + T - 1) / T, T>>>(startp, cnt, csr, dinv, h1, b1, o1, 0, half);
    gemm_3xtf32<LAT, true><<<half / 128, 256>>>(o1, W2, h2, 0, half, HID);

    // chain 1 (stream s2): nodes [half, n)  — needs h1 from stream 0
    cudaStreamWaitEvent(s2, ev_g1, 0);
    k_agg128<<<((n - half) * 32 + T - 1) / T, T, 0, s2>>>(startp, cnt, csr, dinv, h1, b1, o1, half, n);
    gemm_3xtf32<LAT, true><<<(n - half + 127) / 128, 256, 0, s2>>>(o1, W2, h2, half, n, HID);
    cudaEventRecord(ev_c1, s2);

    // ---- join: agg64 needs the full h2 ----
    cudaStreamWaitEvent(0, ev_c1, 0);
    k_agg64_relu<<<(n * 32 + T - 1) / T, T>>>(startp, cnt, csr, dinv, h2, b2, out, n);
}

// round 12
// speedup vs baseline: 2.1083x; 1.0449x over previous
#include <cuda_runtime.h>
#include <cuda_fp16.h>
#include <cuda_bf16.h>
#include <cstdint>

#define NN 50000
#define EE 800000
#define IN_CH 256
#define HID 128
#define LAT 64
#define NB_SCAN ((NN + 255) / 256)   // 196

// ---------------- scratch (device globals; no allocation allowed) -------------
__device__ int      g_anynz;
__device__ int      g_cnt[NN];
__device__ int      g_cursor[NN];
__device__ int      g_start[NN];
__device__ unsigned g_scan_pack[NB_SCAN];  // bits31-30: 0=none,1=agg,2=incl; bits29-0: value
__device__ unsigned g_scan_ctr;
__device__ int      g_csr_src[EE];
__device__ float    g_dinv[NN];
__device__ __half2  g_h1h[(size_t)NN * (HID / 2)];  // fp16 h1 (gather source)
__device__ float    g_o1[(size_t)NN * HID];         // fp32 agg result (GEMM2 input)
__device__ __half2  g_h2h[(size_t)NN * (LAT / 2)];  // fp16 h2 (gather source)

// ---------------- reset + dtype probe (fused) ---------------------------------
__global__ void k_reset_detect(const int* __restrict__ ei32, int* cnt, int n, int e,
                               int nblk) {
    int i = blockIdx.x * blockDim.x + threadIdx.x;
    if (i == 0) { g_anynz = 0; g_scan_ctr = 0; }
    if (i < n) cnt[i] = 0;
    if (i < nblk) g_scan_pack[i] = 0;
    if (i < 1024) {
        long long k = (long long)i * (e / 1024);
        if (ei32[2 * k + 1] != 0) atomicOr(&g_anynz, 1);
    }
}

// histogram straight from edge_index (no unpack pass)
__global__ void k_hist(const int* __restrict__ ei32, int* cnt, int e) {
    int i = blockIdx.x * blockDim.x + threadIdx.x;
    if (i >= e) return;
    int d = (g_anynz == 0) ? ei32[2 * ((size_t)e + i)] : ei32[e + i];
    atomicAdd(&cnt[d], 1);
}

// ---------------- single-pass decoupled-lookback scan --------------------------
__global__ void __launch_bounds__(256) k_scan_lookback(
    const int* __restrict__ cnt, int* start, int* cursor, float* dinv, int n)
{
    __shared__ int s[256];
    __shared__ int sbid;
    __shared__ int sprefix;
    const int tid = threadIdx.x;
    if (tid == 0) sbid = (int)atomicAdd(&g_scan_ctr, 1u);
    __syncthreads();
    const int bid = sbid;
    const int i = bid * 256 + tid;
    const int v = (i < n) ? cnt[i] : 0;

    s[tid] = v;
    __syncthreads();
    for (int off = 1; off < 256; off <<= 1) {
        int t = (tid >= off) ? s[tid - off] : 0;
        __syncthreads();
        s[tid] += t;
        __syncthreads();
    }
    const int total = s[255];

    if (tid == 0) {
        unsigned st = (bid == 0) ? 2u : 1u;
        atomicExch(&g_scan_pack[bid], (st << 30) | (unsigned)total);
    }

    if (tid < 32) {
        int prefix = 0;
        if (bid > 0) {
            int j = bid - 1;
            bool done = false;
            while (!done) {
                int idx = j - tid;
                unsigned p;
                if (idx >= 0) {
                    do { p = *(volatile unsigned*)&g_scan_pack[idx]; } while ((p >> 30) == 0u);
                } else {
                    p = (2u << 30);
                }
                unsigned stt = p >> 30;
                int val = (int)(p & 0x3FFFFFFFu);
                unsigned incl_mask = __ballot_sync(0xFFFFFFFFu, stt == 2u);
                int firstIncl = __ffs(incl_mask) - 1;
                int contrib;
                if (firstIncl >= 0) {
                    contrib = (tid <= firstIncl) ? val : 0;
                    done = true;
                } else {
                    contrib = (idx >= 0) ? val : 0;
                    j -= 32;
                }
#pragma unroll
                for (int o = 16; o; o >>= 1) contrib += __shfl_down_sync(0xFFFFFFFFu, contrib, o);
                prefix += __shfl_sync(0xFFFFFFFFu, contrib, 0);
            }
        }
        if (tid == 0) {
            sprefix = prefix;
            if (bid > 0)
                atomicExch(&g_scan_pack[bid], (2u << 30) | (unsigned)(prefix + total));
        }
    }
    __syncthreads();

    if (i < n) {
        int st = sprefix + s[tid] - v;
        start[i] = st;
        cursor[i] = st;
        dinv[i] = rsqrtf((float)(v + 1));
    }
}

// bucket fill straight from edge_index
__global__ void k_fill(const int* __restrict__ ei32, int* cursor, int* csr, int e) {
    int i = blockIdx.x * blockDim.x + threadIdx.x;
    if (i >= e) return;
    int s, d;
    if (g_anynz == 0) {
        s = ei32[2 * (size_t)i];
        d = ei32[2 * ((size_t)e + i)];
    } else {
        s = ei32[i];
        d = ei32[e + i];
    }
    int pos = atomicAdd(&cursor[d], 1);
    csr[pos] = s;
}

// ---------------- 3xTF32 tensor-core GEMM, fp16 output ------------------------
__device__ __forceinline__ void mma_tf32(float4& d,
                                         uint32_t a0, uint32_t a1, uint32_t a2, uint32_t a3,
                                         uint32_t b0, uint32_t b1) {
    asm volatile(
        "mma.sync.aligned.m16n8k8.row.col.f32.tf32.tf32.f32 "
        "{%0,%1,%2,%3}, {%4,%5,%6,%7}, {%8,%9}, {%0,%1,%2,%3};"
        : "+f"(d.x), "+f"(d.y), "+f"(d.z), "+f"(d.w)
        : "r"(a0), "r"(a1), "r"(a2), "r"(a3), "r"(b0), "r"(b1));
}

__device__ __forceinline__ void split_tf32(float f, uint32_t& hi, uint32_t& lo) {
    uint32_t h = __float_as_uint(f) & 0xFFFFE000u;
    hi = h;
    lo = __float_as_uint(f - __uint_as_float(h));
}

template <int BN, bool RELU_A>
__global__ void __launch_bounds__(256) gemm_3xtf32_h(
    const float* __restrict__ A, const float* __restrict__ B,
    __half2* __restrict__ Ch, int m_lo, int m_hi, int K)
{
    constexpr int BM = 128, BK = 32;
    constexpr int NT = BN / 16;
    constexpr int NBV = BN / 32;
    __shared__ float As[BM][BK + 4];
    __shared__ float Bs[BK][BN + 8];

    const int tid    = threadIdx.x;
    const int warp   = tid >> 5;
    const int lane   = tid & 31;
    const int warp_m = warp & 3;
    const int warp_n = warp >> 2;
    const int m0     = m_lo + blockIdx.x * BM;
    const int qr     = lane >> 2;
    const int qc     = lane & 3;

    const int am  = tid >> 3;
    const int ak4 = (tid & 7) << 2;
    const int bk  = tid / (BN / 4);
    const int bn4 = (tid % (BN / 4)) << 2;
    const int bkStride = 256 / (BN / 4);

    float4 acc[2][NT];
#pragma unroll
    for (int i = 0; i < 2; i++)
#pragma unroll
        for (int j = 0; j < NT; j++) acc[i][j] = make_float4(0.f, 0.f, 0.f, 0.f);

    // ---- load tile 0 ----
#pragma unroll
    for (int i = 0; i < 4; i++) {
        int m = am + i * 32;
        float4 v = make_float4(0.f, 0.f, 0.f, 0.f);
        if (m0 + m < m_hi)
            v = *(const float4*)(A + (size_t)(m0 + m) * K + ak4);
        if (RELU_A) {
            v.x = fmaxf(v.x, 0.f); v.y = fmaxf(v.y, 0.f);
            v.z = fmaxf(v.z, 0.f); v.w = fmaxf(v.w, 0.f);
        }
        *(float4*)&As[m][ak4] = v;
    }
#pragma unroll
    for (int i = 0; i < NBV; i++) {
        int k = bk + i * bkStride;
        *(float4*)&Bs[k][bn4] = *(const float4*)(B + (size_t)k * BN + bn4);
    }
    __syncthreads();

    for (int k0 = 0; k0 < K; k0 += BK) {
        const bool has_next = (k0 + BK < K);
        float4 pa[4], pb[NBV];
        if (has_next) {
#pragma unroll
            for (int i = 0; i < 4; i++) {
                int m = am + i * 32;
                float4 v = make_float4(0.f, 0.f, 0.f, 0.f);
                if (m0 + m < m_hi)
                    v = *(const float4*)(A + (size_t)(m0 + m) * K + (k0 + BK) + ak4);
                if (RELU_A) {
                    v.x = fmaxf(v.x, 0.f); v.y = fmaxf(v.y, 0.f);
                    v.z = fmaxf(v.z, 0.f); v.w = fmaxf(v.w, 0.f);
                }
                pa[i] = v;
            }
#pragma unroll
            for (int i = 0; i < NBV; i++) {
                int k = bk + i * bkStride;
                pb[i] = *(const float4*)(B + (size_t)(k0 + BK + k) * BN + bn4);
            }
        }

#pragma unroll
        for (int ks = 0; ks < 4; ks++) {
            const int c = ks * 8;
            uint32_t ah[2][4], al[2][4];
#pragma unroll
            for (int mt = 0; mt < 2; mt++) {
                int r = warp_m * 32 + mt * 16 + qr;
                split_tf32(As[r][c + qc],         ah[mt][0], al[mt][0]);
                split_tf32(As[r + 8][c + qc],     ah[mt][1], al[mt][1]);
                split_tf32(As[r][c + qc + 4],     ah[mt][2], al[mt][2]);
                split_tf32(As[r + 8][c + qc + 4], ah[mt][3], al[mt][3]);
            }
            uint32_t bh[NT][2], bl[NT][2];
#pragma unroll
            for (int nt = 0; nt < NT; nt++) {
                int nn = warp_n * (NT * 8) + nt * 8 + qr;
                split_tf32(Bs[c + qc][nn],     bh[nt][0], bl[nt][0]);
                split_tf32(Bs[c + qc + 4][nn], bh[nt][1], bl[nt][1]);
            }
#pragma unroll
            for (int mt = 0; mt < 2; mt++)
#pragma unroll
                for (int nt = 0; nt < NT; nt++) {
                    mma_tf32(acc[mt][nt], al[mt][0], al[mt][1], al[mt][2], al[mt][3],
                             bh[nt][0], bh[nt][1]);
                    mma_tf32(acc[mt][nt], ah[mt][0], ah[mt][1], ah[mt][2], ah[mt][3],
                             bl[nt][0], bl[nt][1]);
                    mma_tf32(acc[mt][nt], ah[mt][0], ah[mt][1], ah[mt][2], ah[mt][3],
                             bh[nt][0], bh[nt][1]);
                }
        }
        __syncthreads();

        if (has_next) {
#pragma unroll
            for (int i = 0; i < 4; i++)
                *(float4*)&As[am + i * 32][ak4] = pa[i];
#pragma unroll
            for (int i = 0; i < NBV; i++)
                *(float4*)&Bs[bk + i * bkStride][bn4] = pb[i];
            __syncthreads();
        }
    }

    // --- epilogue: fp16 output; (c0,c1)/(c2,c3) are adjacent columns ---
#pragma unroll
    for (int mt = 0; mt < 2; mt++) {
        int row = m0 + warp_m * 32 + mt * 16 + qr;
#pragma unroll
        for (int nt = 0; nt < NT; nt++) {
            int col2 = (warp_n * (NT * 8) + nt * 8 + 2 * qc) >> 1;   // half2 index
            if (row < m_hi)
                Ch[(size_t)row * (BN / 2) + col2] = __floats2half2_rn(acc[mt][nt].x, acc[mt][nt].y);
            if (row + 8 < m_hi)
                Ch[(size_t)(row + 8) * (BN / 2) + col2] = __floats2half2_rn(acc[mt][nt].z, acc[mt][nt].w);
        }
    }
}

// ---------------- gather aggregation, 128 feats fp16 in / fp32 out ------------
// out[d] = bias + dinv[d]^2*h[d] + sum dinv[d]*dinv[s]*h[s];  lane: 4 feats.
__global__ void __launch_bounds__(256) k_agg128(
    const int* __restrict__ start, const int* __restrict__ cnt,
    const int* __restrict__ csr, const float* __restrict__ dinv,
    const __half2* __restrict__ h, const float* __restrict__ bias,
    float* __restrict__ out, int n_lo, int n_hi)
{
    int d = n_lo + ((blockIdx.x * blockDim.x + threadIdx.x) >> 5);
    int lane = threadIdx.x & 31;
    if (d >= n_hi) return;
    float dd = dinv[d];
    int beg = start[d];
    int num = cnt[d];

    uint2 raw = *(const uint2*)(h + (size_t)d * 64 + lane * 2);
    float2 p0 = __half22float2(*(__half2*)&raw.x);
    float2 p1 = __half22float2(*(__half2*)&raw.y);
    float4 bv = *(const float4*)(bias + lane * 4);
    float sd = dd * dd;
    float4 acc;
    acc.x = fmaf(sd, p0.x, bv.x); acc.y = fmaf(sd, p0.y, bv.y);
    acc.z = fmaf(sd, p1.x, bv.z); acc.w = fmaf(sd, p1.y, bv.w);

#pragma unroll 4
    for (int j = 0; j < num; j++) {
        int s = __ldg(&csr[beg + j]);
        float nrm = dd * __ldg(&dinv[s]);
        uint2 r = *(const uint2*)(h + (size_t)s * 64 + lane * 2);
        float2 v0 = __half22float2(*(__half2*)&r.x);
        float2 v1 = __half22float2(*(__half2*)&r.y);
        acc.x = fmaf(nrm, v0.x, acc.x); acc.y = fmaf(nrm, v0.y, acc.y);
        acc.z = fmaf(nrm, v1.x, acc.z); acc.w = fmaf(nrm, v1.y, acc.w);
    }
    *(float4*)(out + (size_t)d * 128 + lane * 4) = acc;
}

// ---------------- gather aggregation, 64 feats fp16 in + fused final relu -----
__global__ void __launch_bounds__(256) k_agg64_relu(
    const int* __restrict__ start, const int* __restrict__ cnt,
    const int* __restrict__ csr, const float* __restrict__ dinv,
    const __half2* __restrict__ h, const float* __restrict__ bias,
    float* __restrict__ out, int n)
{
    int d = (blockIdx.x * blockDim.x + threadIdx.x) >> 5;
    int lane = threadIdx.x & 31;
    if (d >= n) return;
    float dd = dinv[d];
    int beg = start[d];
    int num = cnt[d];

    float2 hv = __half22float2(h[(size_t)d * 32 + lane]);
    float2 bv = *(const float2*)(bias + lane * 2);
    float sd = dd * dd;
    float2 acc;
    acc.x = fmaf(sd, hv.x, bv.x); acc.y = fmaf(sd, hv.y, bv.y);

#pragma unroll 4
    for (int j = 0; j < num; j++) {
        int s = __ldg(&csr[beg + j]);
        float nrm = dd * __ldg(&dinv[s]);
        float2 v = __half22float2(__ldg(h + (size_t)s * 32 + lane));
        acc.x = fmaf(nrm, v.x, acc.x); acc.y = fmaf(nrm, v.y, acc.y);
    }
    acc.x = fmaxf(acc.x, 0.f);
    acc.y = fmaxf(acc.y, 0.f);
    *(float2*)(out + (size_t)d * 64 + lane * 2) = acc;
}

// ==============================================================================
extern "C" void kernel_launch(void* const* d_in, const int* in_sizes, int n_in,
                              void* d_out, int out_size)
{
    const float* x    = (const float*)d_in[0];   // [N, 256]
    const int*   ei32 = (const int*)d_in[1];     // [2, E] int32 OR int64 (probed)
    const float* W1   = (const float*)d_in[2];   // [256, 128]
    const float* b1   = (const float*)d_in[3];   // [128]
    const float* W2   = (const float*)d_in[4];   // [128, 64]
    const float* b2   = (const float*)d_in[5];   // [64]
    float*       out  = (float*)d_out;           // [N, 64]

    const int n = in_sizes[0] / IN_CH;   // 50000
    const int e = in_sizes[1] / 2;       // 800000

    int *cnt, *cursor, *startp, *csr;
    float *dinv, *o1;
    __half2 *h1h, *h2h;
    cudaGetSymbolAddress((void**)&cnt,    g_cnt);
    cudaGetSymbolAddress((void**)&cursor, g_cursor);
    cudaGetSymbolAddress((void**)&startp, g_start);
    cudaGetSymbolAddress((void**)&csr,    g_csr_src);
    cudaGetSymbolAddress((void**)&dinv,   g_dinv);
    cudaGetSymbolAddress((void**)&h1h,    g_h1h);
    cudaGetSymbolAddress((void**)&o1,     g_o1);
    cudaGetSymbolAddress((void**)&h2h,    g_h2h);

    // side stream + events, created once on the first (uncaptured) call
    static cudaStream_t s2 = nullptr;
    static cudaEvent_t  ev_fork = nullptr, ev_csr = nullptr,
                        ev_g1 = nullptr, ev_c1 = nullptr;
    if (s2 == nullptr) {
        cudaStreamCreateWithFlags(&s2, cudaStreamNonBlocking);
        cudaEventCreateWithFlags(&ev_fork, cudaEventDisableTiming);
        cudaEventCreateWithFlags(&ev_csr,  cudaEventDisableTiming);
        cudaEventCreateWithFlags(&ev_g1,   cudaEventDisableTiming);
        cudaEventCreateWithFlags(&ev_c1,   cudaEventDisableTiming);
    }

    const int T = 256;
    const int nb = (n + T - 1) / T;
    const int eb = (e + T - 1) / T;
    const int half = ((n / 2) + 127) & ~127;     // chunk boundary, 128-aligned

    // ---- fork: CSR build chain on s2, concurrent with GEMM1 on stream 0 ----
    cudaEventRecord(ev_fork, 0);
    cudaStreamWaitEvent(s2, ev_fork, 0);

    k_reset_detect <<<nb, T, 0, s2>>>(ei32, cnt, n, e, nb);
    k_hist         <<<eb, T, 0, s2>>>(ei32, cnt, e);
    k_scan_lookback<<<nb, T, 0, s2>>>(cnt, startp, cursor, dinv, n);
    k_fill         <<<eb, T, 0, s2>>>(ei32, cursor, csr, e);
    cudaEventRecord(ev_csr, s2);

    // GEMM1 on the main stream (fp16 output), overlapping the CSR build
    gemm_3xtf32_h<HID, false><<<(n + 127) / 128, 256>>>(x, W1, h1h, 0, n, IN_CH);
    cudaEventRecord(ev_g1, 0);

    // ---- chunked layer-1 agg + layer-2 GEMM, two independent chains --------
    // chain 0 (stream 0): nodes [0, half)   — needs CSR from s2
    cudaStreamWaitEvent(0, ev_csr, 0);
    k_agg128<<<(half * 32 + T - 1) / T, T>>>(startp, cnt, csr, dinv, h1h, b1, o1, 0, half);
    gemm_3xtf32_h<LAT, true><<<half / 128, 256>>>(o1, W2, h2h, 0, half, HID);

    // chain 1 (stream s2): nodes [half, n)  — needs h1 from stream 0
    cudaStreamWaitEvent(s2, ev_g1, 0);
    k_agg128<<<((n - half) * 32 + T - 1) / T, T, 0, s2>>>(startp, cnt, csr, dinv, h1h, b1, o1, half, n);
    gemm_3xtf32_h<LAT, true><<<(n - half + 127) / 128, 256, 0, s2>>>(o1, W2, h2h, half, n, HID);
    cudaEventRecord(ev_c1, s2);

    // ---- join: agg64 needs the full h2 ----
    cudaStreamWaitEvent(0, ev_c1, 0);
    k_agg64_relu<<<(n * 32 + T - 1) / T, T>>>(startp, cnt, csr, dinv, h2h, b2, out, n);
}

// round 13
// speedup vs baseline: 2.6136x; 1.2397x over previous
#include <cuda_runtime.h>
#include <cuda_fp16.h>
#include <cuda_bf16.h>
#include <cstdint>

#define NN 50000
#define EE 800000
#define IN_CH 256
#define HID 128
#define LAT 64
#define NB_SCAN ((NN + 255) / 256)   // 196

// ---------------- scratch (device globals; no allocation allowed) -------------
__device__ int      g_anynz;
__device__ int      g_cnt[NN];
__device__ int      g_start[NN];
__device__ int      g_rank[EE];            // per-edge rank within its dst bucket
__device__ unsigned g_scan_pack[NB_SCAN];  // bits31-30: 0=none,1=agg,2=incl
__device__ unsigned g_scan_ctr;
__device__ int      g_csr_src[EE];
__device__ float    g_dinv[NN];
__device__ __half2  g_h1h[(size_t)NN * (HID / 2)];
__device__ float    g_o1[(size_t)NN * HID];
__device__ __half2  g_h2h[(size_t)NN * (LAT / 2)];

// ---------------- reset + dtype probe (fused) ---------------------------------
__global__ void k_reset_detect(const int* __restrict__ ei32, int* cnt, int n, int e,
                               int nblk) {
    int i = blockIdx.x * blockDim.x + threadIdx.x;
    if (i == 0) { g_anynz = 0; g_scan_ctr = 0; }
    if (i < n) cnt[i] = 0;
    if (i < nblk) g_scan_pack[i] = 0;
    if (i < 1024) {
        long long k = (long long)i * (e / 1024);
        if (ei32[2 * k + 1] != 0) atomicOr(&g_anynz, 1);
    }
}

// histogram + per-edge bucket rank (the atomic's return value)
__global__ void k_hist_rank(const int* __restrict__ ei32, int* cnt, int* rank, int e) {
    int i = blockIdx.x * blockDim.x + threadIdx.x;
    if (i >= e) return;
    int d = (g_anynz == 0) ? ei32[2 * ((size_t)e + i)] : ei32[e + i];
    rank[i] = atomicAdd(&cnt[d], 1);
}

// ---------------- single-pass decoupled-lookback scan --------------------------
__global__ void __launch_bounds__(256) k_scan_lookback(
    const int* __restrict__ cnt, int* start, float* dinv, int n)
{
    __shared__ int s[256];
    __shared__ int sbid;
    __shared__ int sprefix;
    const int tid = threadIdx.x;
    if (tid == 0) sbid = (int)atomicAdd(&g_scan_ctr, 1u);
    __syncthreads();
    const int bid = sbid;
    const int i = bid * 256 + tid;
    const int v = (i < n) ? cnt[i] : 0;

    s[tid] = v;
    __syncthreads();
    for (int off = 1; off < 256; off <<= 1) {
        int t = (tid >= off) ? s[tid - off] : 0;
        __syncthreads();
        s[tid] += t;
        __syncthreads();
    }
    const int total = s[255];

    if (tid == 0) {
        unsigned st = (bid == 0) ? 2u : 1u;
        atomicExch(&g_scan_pack[bid], (st << 30) | (unsigned)total);
    }

    if (tid < 32) {
        int prefix = 0;
        if (bid > 0) {
            int j = bid - 1;
            bool done = false;
            while (!done) {
                int idx = j - tid;
                unsigned p;
                if (idx >= 0) {
                    do { p = *(volatile unsigned*)&g_scan_pack[idx]; } while ((p >> 30) == 0u);
                } else {
                    p = (2u << 30);
                }
                unsigned stt = p >> 30;
                int val = (int)(p & 0x3FFFFFFFu);
                unsigned incl_mask = __ballot_sync(0xFFFFFFFFu, stt == 2u);
                int firstIncl = __ffs(incl_mask) - 1;
                int contrib;
                if (firstIncl >= 0) {
                    contrib = (tid <= firstIncl) ? val : 0;
                    done = true;
                } else {
                    contrib = (idx >= 0) ? val : 0;
                    j -= 32;
                }
#pragma unroll
                for (int o = 16; o; o >>= 1) contrib += __shfl_down_sync(0xFFFFFFFFu, contrib, o);
                prefix += __shfl_sync(0xFFFFFFFFu, contrib, 0);
            }
        }
        if (tid == 0) {
            sprefix = prefix;
            if (bid > 0)
                atomicExch(&g_scan_pack[bid], (2u << 30) | (unsigned)(prefix + total));
        }
    }
    __syncthreads();

    if (i < n) {
        start[i] = sprefix + s[tid] - v;
        dinv[i] = rsqrtf((float)(v + 1));
    }
}

// atomic-free bucket fill: position = start[dst] + precomputed rank
__global__ void k_fill_rank(const int* __restrict__ ei32, const int* __restrict__ start,
                            const int* __restrict__ rank, int* csr, int e) {
    int i = blockIdx.x * blockDim.x + threadIdx.x;
    if (i >= e) return;
    int s, d;
    if (g_anynz == 0) {            // int64 little-endian: low word carries index
        s = ei32[2 * (size_t)i];
        d = ei32[2 * ((size_t)e + i)];
    } else {                       // int32
        s = ei32[i];
        d = ei32[e + i];
    }
    csr[start[d] + rank[i]] = s;
}

// ---------------- fp16 tensor-core GEMM1: C[M,128] = A[M,256] @ B[256,128] ----
// m16n8k16 f16 MMA, fp32 accumulate, fp16 output. BM=128, BK=32, 8 warps 4x2.
__device__ __forceinline__ void mma_f16(float4& d,
                                        uint32_t a0, uint32_t a1, uint32_t a2, uint32_t a3,
                                        uint32_t b0, uint32_t b1) {
    asm volatile(
        "mma.sync.aligned.m16n8k16.row.col.f32.f16.f16.f32 "
        "{%0,%1,%2,%3}, {%4,%5,%6,%7}, {%8,%9}, {%0,%1,%2,%3};"
        : "+f"(d.x), "+f"(d.y), "+f"(d.z), "+f"(d.w)
        : "r"(a0), "r"(a1), "r"(a2), "r"(a3), "r"(b0), "r"(b1));
}

__global__ void __launch_bounds__(256) gemm_f16_h(
    const float* __restrict__ A, const float* __restrict__ B,
    __half2* __restrict__ Ch, int M, int K)   // K=256, N=128 fixed
{
    constexpr int BM = 128, BK = 32, BN = 128;
    constexpr int NT = BN / 16;              // 8 n8-tiles per warp
    __shared__ __half As[BM][BK + 8];        // pad 8 halves (16B)
    __shared__ __half Bs[BK][BN + 8];

    const int tid    = threadIdx.x;
    const int warp   = tid >> 5;
    const int lane   = tid & 31;
    const int warp_m = warp & 3;
    const int warp_n = warp >> 2;
    const int m0     = blockIdx.x * BM;
    const int qr     = lane >> 2;            // group id 0..7
    const int qc     = lane & 3;             // thread-in-group 0..3

    const int am  = tid >> 3;                // A row
    const int ak4 = (tid & 7) << 2;          // A k offset (float4)
    const int bk  = tid >> 5;                // B k row (stride 8)
    const int bn4 = (tid & 31) << 2;         // B n offset (float4)

    float4 acc[2][NT];
#pragma unroll
    for (int i = 0; i < 2; i++)
#pragma unroll
        for (int j = 0; j < NT; j++) acc[i][j] = make_float4(0.f, 0.f, 0.f, 0.f);

    // ---- load tile 0 (fp32 -> fp16) ----
#pragma unroll
    for (int i = 0; i < 4; i++) {
        int m = am + i * 32;
        float4 v = make_float4(0.f, 0.f, 0.f, 0.f);
        if (m0 + m < M)
            v = *(const float4*)(A + (size_t)(m0 + m) * K + ak4);
        __half2 h0 = __floats2half2_rn(v.x, v.y);
        __half2 h1 = __floats2half2_rn(v.z, v.w);
        *(__half2*)&As[m][ak4]     = h0;
        *(__half2*)&As[m][ak4 + 2] = h1;
    }
#pragma unroll
    for (int i = 0; i < 4; i++) {
        int k = bk + i * 8;
        float4 v = *(const float4*)(B + (size_t)k * BN + bn4);
        *(__half2*)&Bs[k][bn4]     = __floats2half2_rn(v.x, v.y);
        *(__half2*)&Bs[k][bn4 + 2] = __floats2half2_rn(v.z, v.w);
    }
    __syncthreads();

    for (int k0 = 0; k0 < K; k0 += BK) {
        const bool has_next = (k0 + BK < K);
        float4 pa[4], pb[4];
        if (has_next) {
#pragma unroll
            for (int i = 0; i < 4; i++) {
                int m = am + i * 32;
                pa[i] = make_float4(0.f, 0.f, 0.f, 0.f);
                if (m0 + m < M)
                    pa[i] = *(const float4*)(A + (size_t)(m0 + m) * K + (k0 + BK) + ak4);
            }
#pragma unroll
            for (int i = 0; i < 4; i++) {
                int k = bk + i * 8;
                pb[i] = *(const float4*)(B + (size_t)(k0 + BK + k) * BN + bn4);
            }
        }

        // ---- compute: 2 k16 steps ----
#pragma unroll
        for (int ks = 0; ks < 2; ks++) {
            const int c = ks * 16;
            uint32_t a[2][4];
#pragma unroll
            for (int mt = 0; mt < 2; mt++) {
                int r = warp_m * 32 + mt * 16 + qr;
                a[mt][0] = *(const uint32_t*)&As[r][c + 2 * qc];
                a[mt][1] = *(const uint32_t*)&As[r + 8][c + 2 * qc];
                a[mt][2] = *(const uint32_t*)&As[r][c + 2 * qc + 8];
                a[mt][3] = *(const uint32_t*)&As[r + 8][c + 2 * qc + 8];
            }
            uint32_t b[NT][2];
#pragma unroll
            for (int nt = 0; nt < NT; nt++) {
                int nn = warp_n * (NT * 8) + nt * 8 + qr;
                __half2 b0 = __halves2half2(Bs[c + 2 * qc][nn],     Bs[c + 2 * qc + 1][nn]);
                __half2 b1 = __halves2half2(Bs[c + 2 * qc + 8][nn], Bs[c + 2 * qc + 9][nn]);
                b[nt][0] = *(uint32_t*)&b0;
                b[nt][1] = *(uint32_t*)&b1;
            }
#pragma unroll
            for (int mt = 0; mt < 2; mt++)
#pragma unroll
                for (int nt = 0; nt < NT; nt++)
                    mma_f16(acc[mt][nt], a[mt][0], a[mt][1], a[mt][2], a[mt][3],
                            b[nt][0], b[nt][1]);
        }
        __syncthreads();

        if (has_next) {
#pragma unroll
            for (int i = 0; i < 4; i++) {
                int m = am + i * 32;
                *(__half2*)&As[m][ak4]     = __floats2half2_rn(pa[i].x, pa[i].y);
                *(__half2*)&As[m][ak4 + 2] = __floats2half2_rn(pa[i].z, pa[i].w);
            }
#pragma unroll
            for (int i = 0; i < 4; i++) {
                int k = bk + i * 8;
                *(__half2*)&Bs[k][bn4]     = __floats2half2_rn(pb[i].x, pb[i].y);
                *(__half2*)&Bs[k][bn4 + 2] = __floats2half2_rn(pb[i].z, pb[i].w);
            }
            __syncthreads();
        }
    }

    // --- epilogue: fp16 output; (c0,c1)/(c2,c3) are adjacent columns ---
#pragma unroll
    for (int mt = 0; mt < 2; mt++) {
        int row = m0 + warp_m * 32 + mt * 16 + qr;
#pragma unroll
        for (int nt = 0; nt < NT; nt++) {
            int col2 = (warp_n * (NT * 8) + nt * 8 + 2 * qc) >> 1;
            if (row < M)
                Ch[(size_t)row * (BN / 2) + col2] = __floats2half2_rn(acc[mt][nt].x, acc[mt][nt].y);
            if (row + 8 < M)
                Ch[(size_t)(row + 8) * (BN / 2) + col2] = __floats2half2_rn(acc[mt][nt].z, acc[mt][nt].w);
        }
    }
}

// ---------------- 3xTF32 tensor-core GEMM (layer 2), fp16 output --------------
__device__ __forceinline__ void mma_tf32(float4& d,
                                         uint32_t a0, uint32_t a1, uint32_t a2, uint32_t a3,
                                         uint32_t b0, uint32_t b1) {
    asm volatile(
        "mma.sync.aligned.m16n8k8.row.col.f32.tf32.tf32.f32 "
        "{%0,%1,%2,%3}, {%4,%5,%6,%7}, {%8,%9}, {%0,%1,%2,%3};"
        : "+f"(d.x), "+f"(d.y), "+f"(d.z), "+f"(d.w)
        : "r"(a0), "r"(a1), "r"(a2), "r"(a3), "r"(b0), "r"(b1));
}

__device__ __forceinline__ void split_tf32(float f, uint32_t& hi, uint32_t& lo) {
    uint32_t h = __float_as_uint(f) & 0xFFFFE000u;
    hi = h;
    lo = __float_as_uint(f - __uint_as_float(h));
}

template <int BN, bool RELU_A>
__global__ void __launch_bounds__(256) gemm_3xtf32_h(
    const float* __restrict__ A, const float* __restrict__ B,
    __half2* __restrict__ Ch, int m_lo, int m_hi, int K)
{
    constexpr int BM = 128, BK = 32;
    constexpr int NT = BN / 16;
    constexpr int NBV = BN / 32;
    __shared__ float As[BM][BK + 4];
    __shared__ float Bs[BK][BN + 8];

    const int tid    = threadIdx.x;
    const int warp   = tid >> 5;
    const int lane   = tid & 31;
    const int warp_m = warp & 3;
    const int warp_n = warp >> 2;
    const int m0     = m_lo + blockIdx.x * BM;
    const int qr     = lane >> 2;
    const int qc     = lane & 3;

    const int am  = tid >> 3;
    const int ak4 = (tid & 7) << 2;
    const int bk  = tid / (BN / 4);
    const int bn4 = (tid % (BN / 4)) << 2;
    const int bkStride = 256 / (BN / 4);

    float4 acc[2][NT];
#pragma unroll
    for (int i = 0; i < 2; i++)
#pragma unroll
        for (int j = 0; j < NT; j++) acc[i][j] = make_float4(0.f, 0.f, 0.f, 0.f);

#pragma unroll
    for (int i = 0; i < 4; i++) {
        int m = am + i * 32;
        float4 v = make_float4(0.f, 0.f, 0.f, 0.f);
        if (m0 + m < m_hi)
            v = *(const float4*)(A + (size_t)(m0 + m) * K + ak4);
        if (RELU_A) {
            v.x = fmaxf(v.x, 0.f); v.y = fmaxf(v.y, 0.f);
            v.z = fmaxf(v.z, 0.f); v.w = fmaxf(v.w, 0.f);
        }
        *(float4*)&As[m][ak4] = v;
    }
#pragma unroll
    for (int i = 0; i < NBV; i++) {
        int k = bk + i * bkStride;
        *(float4*)&Bs[k][bn4] = *(const float4*)(B + (size_t)k * BN + bn4);
    }
    __syncthreads();

    for (int k0 = 0; k0 < K; k0 += BK) {
        const bool has_next = (k0 + BK < K);
        float4 pa[4], pb[NBV];
        if (has_next) {
#pragma unroll
            for (int i = 0; i < 4; i++) {
                int m = am + i * 32;
                float4 v = make_float4(0.f, 0.f, 0.f, 0.f);
                if (m0 + m < m_hi)
                    v = *(const float4*)(A + (size_t)(m0 + m) * K + (k0 + BK) + ak4);
                if (RELU_A) {
                    v.x = fmaxf(v.x, 0.f); v.y = fmaxf(v.y, 0.f);
                    v.z = fmaxf(v.z, 0.f); v.w = fmaxf(v.w, 0.f);
                }
                pa[i] = v;
            }
#pragma unroll
            for (int i = 0; i < NBV; i++) {
                int k = bk + i * bkStride;
                pb[i] = *(const float4*)(B + (size_t)(k0 + BK + k) * BN + bn4);
            }
        }

#pragma unroll
        for (int ks = 0; ks < 4; ks++) {
            const int c = ks * 8;
            uint32_t ah[2][4], al[2][4];
#pragma unroll
            for (int mt = 0; mt < 2; mt++) {
                int r = warp_m * 32 + mt * 16 + qr;
                split_tf32(As[r][c + qc],         ah[mt][0], al[mt][0]);
                split_tf32(As[r + 8][c + qc],     ah[mt][1], al[mt][1]);
                split_tf32(As[r][c + qc + 4],     ah[mt][2], al[mt][2]);
                split_tf32(As[r + 8][c + qc + 4], ah[mt][3], al[mt][3]);
            }
            uint32_t bh[NT][2], bl[NT][2];
#pragma unroll
            for (int nt = 0; nt < NT; nt++) {
                int nn = warp_n * (NT * 8) + nt * 8 + qr;
                split_tf32(Bs[c + qc][nn],     bh[nt][0], bl[nt][0]);
                split_tf32(Bs[c + qc + 4][nn], bh[nt][1], bl[nt][1]);
            }
#pragma unroll
            for (int mt = 0; mt < 2; mt++)
#pragma unroll
                for (int nt = 0; nt < NT; nt++) {
                    mma_tf32(acc[mt][nt], al[mt][0], al[mt][1], al[mt][2], al[mt][3],
                             bh[nt][0], bh[nt][1]);
                    mma_tf32(acc[mt][nt], ah[mt][0], ah[mt][1], ah[mt][2], ah[mt][3],
                             bl[nt][0], bl[nt][1]);
                    mma_tf32(acc[mt][nt], ah[mt][0], ah[mt][1], ah[mt][2], ah[mt][3],
                             bh[nt][0], bh[nt][1]);
                }
        }
        __syncthreads();

        if (has_next) {
#pragma unroll
            for (int i = 0; i < 4; i++)
                *(float4*)&As[am + i * 32][ak4] = pa[i];
#pragma unroll
            for (int i = 0; i < NBV; i++)
                *(float4*)&Bs[bk + i * bkStride][bn4] = pb[i];
            __syncthreads();
        }
    }

#pragma unroll
    for (int mt = 0; mt < 2; mt++) {
        int row = m0 + warp_m * 32 + mt * 16 + qr;
#pragma unroll
        for (int nt = 0; nt < NT; nt++) {
            int col2 = (warp_n * (NT * 8) + nt * 8 + 2 * qc) >> 1;
            if (row < m_hi)
                Ch[(size_t)row * (BN / 2) + col2] = __floats2half2_rn(acc[mt][nt].x, acc[mt][nt].y);
            if (row + 8 < m_hi)
                Ch[(size_t)(row + 8) * (BN / 2) + col2] = __floats2half2_rn(acc[mt][nt].z, acc[mt][nt].w);
        }
    }
}

// ---------------- gather aggregation, 128 feats fp16 in / fp32 out ------------
__global__ void __launch_bounds__(256) k_agg128(
    const int* __restrict__ start, const int* __restrict__ cnt,
    const int* __restrict__ csr, const float* __restrict__ dinv,
    const __half2* __restrict__ h, const float* __restrict__ bias,
    float* __restrict__ out, int n_lo, int n_hi)
{
    int d = n_lo + ((blockIdx.x * blockDim.x + threadIdx.x) >> 5);
    int lane = threadIdx.x & 31;
    if (d >= n_hi) return;
    float dd = dinv[d];
    int beg = start[d];
    int num = cnt[d];

    uint2 raw = *(const uint2*)(h + (size_t)d * 64 + lane * 2);
    float2 p0 = __half22float2(*(__half2*)&raw.x);
    float2 p1 = __half22float2(*(__half2*)&raw.y);
    float4 bv = *(const float4*)(bias + lane * 4);
    float sd = dd * dd;
    float4 acc;
    acc.x = fmaf(sd, p0.x, bv.x); acc.y = fmaf(sd, p0.y, bv.y);
    acc.z = fmaf(sd, p1.x, bv.z); acc.w = fmaf(sd, p1.y, bv.w);

#pragma unroll 4
    for (int j = 0; j < num; j++) {
        int s = __ldg(&csr[beg + j]);
        float nrm = dd * __ldg(&dinv[s]);
        uint2 r = *(const uint2*)(h + (size_t)s * 64 + lane * 2);
        float2 v0 = __half22float2(*(__half2*)&r.x);
        float2 v1 = __half22float2(*(__half2*)&r.y);
        acc.x = fmaf(nrm, v0.x, acc.x); acc.y = fmaf(nrm, v0.y, acc.y);
        acc.z = fmaf(nrm, v1.x, acc.z); acc.w = fmaf(nrm, v1.y, acc.w);
    }
    *(float4*)(out + (size_t)d * 128 + lane * 4) = acc;
}

// ---------------- gather aggregation, 64 feats fp16 in + fused final relu -----
__global__ void __launch_bounds__(256) k_agg64_relu(
    const int* __restrict__ start, const int* __restrict__ cnt,
    const int* __restrict__ csr, const float* __restrict__ dinv,
    const __half2* __restrict__ h, const float* __restrict__ bias,
    float* __restrict__ out, int n)
{
    int d = (blockIdx.x * blockDim.x + threadIdx.x) >> 5;
    int lane = threadIdx.x & 31;
    if (d >= n) return;
    float dd = dinv[d];
    int beg = start[d];
    int num = cnt[d];

    float2 hv = __half22float2(h[(size_t)d * 32 + lane]);
    float2 bv = *(const float2*)(bias + lane * 2);
    float sd = dd * dd;
    float2 acc;
    acc.x = fmaf(sd, hv.x, bv.x); acc.y = fmaf(sd, hv.y, bv.y);

#pragma unroll 4
    for (int j = 0; j < num; j++) {
        int s = __ldg(&csr[beg + j]);
        float nrm = dd * __ldg(&dinv[s]);
        float2 v = __half22float2(__ldg(h + (size_t)s * 32 + lane));
        acc.x = fmaf(nrm, v.x, acc.x); acc.y = fmaf(nrm, v.y, acc.y);
    }
    acc.x = fmaxf(acc.x, 0.f);
    acc.y = fmaxf(acc.y, 0.f);
    *(float2*)(out + (size_t)d * 64 + lane * 2) = acc;
}

// ==============================================================================
extern "C" void kernel_launch(void* const* d_in, const int* in_sizes, int n_in,
                              void* d_out, int out_size)
{
    const float* x    = (const float*)d_in[0];   // [N, 256]
    const int*   ei32 = (const int*)d_in[1];     // [2, E] int32 OR int64 (probed)
    const float* W1   = (const float*)d_in[2];   // [256, 128]
    const float* b1   = (const float*)d_in[3];   // [128]
    const float* W2   = (const float*)d_in[4];   // [128, 64]
    const float* b2   = (const float*)d_in[5];   // [64]
    float*       out  = (float*)d_out;           // [N, 64]

    const int n = in_sizes[0] / IN_CH;   // 50000
    const int e = in_sizes[1] / 2;       // 800000

    int *cnt, *startp, *rank, *csr;
    float *dinv, *o1;
    __half2 *h1h, *h2h;
    cudaGetSymbolAddress((void**)&cnt,    g_cnt);
    cudaGetSymbolAddress((void**)&startp, g_start);
    cudaGetSymbolAddress((void**)&rank,   g_rank);
    cudaGetSymbolAddress((void**)&csr,    g_csr_src);
    cudaGetSymbolAddress((void**)&dinv,   g_dinv);
    cudaGetSymbolAddress((void**)&h1h,    g_h1h);
    cudaGetSymbolAddress((void**)&o1,     g_o1);
    cudaGetSymbolAddress((void**)&h2h,    g_h2h);

    // side stream + events, created once on the first (uncaptured) call
    static cudaStream_t s2 = nullptr;
    static cudaEvent_t  ev_fork = nullptr, ev_csr = nullptr,
                        ev_g1 = nullptr, ev_c1 = nullptr;
    if (s2 == nullptr) {
        cudaStreamCreateWithFlags(&s2, cudaStreamNonBlocking);
        cudaEventCreateWithFlags(&ev_fork, cudaEventDisableTiming);
        cudaEventCreateWithFlags(&ev_csr,  cudaEventDisableTiming);
        cudaEventCreateWithFlags(&ev_g1,   cudaEventDisableTiming);
        cudaEventCreateWithFlags(&ev_c1,   cudaEventDisableTiming);
    }

    const int T = 256;
    const int nb = (n + T - 1) / T;
    const int eb = (e + T - 1) / T;
    const int half = ((n / 2) + 127) & ~127;

    // ---- fork: CSR build chain on s2, concurrent with GEMM1 on stream 0 ----
    cudaEventRecord(ev_fork, 0);
    cudaStreamWaitEvent(s2, ev_fork, 0);

    k_reset_detect <<<nb, T, 0, s2>>>(ei32, cnt, n, e, nb);
    k_hist_rank    <<<eb, T, 0, s2>>>(ei32, cnt, rank, e);
    k_scan_lookback<<<nb, T, 0, s2>>>(cnt, startp, dinv, n);
    k_fill_rank    <<<eb, T, 0, s2>>>(ei32, startp, rank, csr, e);
    cudaEventRecord(ev_csr, s2);

    // GEMM1 (fp16 MMA) on the main stream, overlapping the CSR build
    gemm_f16_h<<<(n + 127) / 128, 256>>>(x, W1, h1h, n, IN_CH);
    cudaEventRecord(ev_g1, 0);

    // ---- chunked layer-1 agg + layer-2 GEMM, two independent chains --------
    cudaStreamWaitEvent(0, ev_csr, 0);
    k_agg128<<<(half * 32 + T - 1) / T, T>>>(startp, cnt, csr, dinv, h1h, b1, o1, 0, half);
    gemm_3xtf32_h<LAT, true><<<half / 128, 256>>>(o1, W2, h2h, 0, half, HID);

    cudaStreamWaitEvent(s2, ev_g1, 0);
    k_agg128<<<((n - half) * 32 + T - 1) / T, T, 0, s2>>>(startp, cnt, csr, dinv, h1h, b1, o1, half, n);
    gemm_3xtf32_h<LAT, true><<<(n - half + 127) / 128, 256, 0, s2>>>(o1, W2, h2h, half, n, HID);
    cudaEventRecord(ev_c1, s2);

    // ---- join: agg64 needs the full h2 ----
    cudaStreamWaitEvent(0, ev_c1, 0);
    k_agg64_relu<<<(n * 32 + T - 1) / T, T>>>(startp, cnt, csr, dinv, h2h, b2, out, n);
}

// round 14
// speedup vs baseline: 2.7761x; 1.0622x over previous
#include <cuda_runtime.h>
#include <cuda_fp16.h>
#include <cuda_bf16.h>
#include <cstdint>

#define NN 50000
#define EE 800000
#define IN_CH 256
#define HID 128
#define LAT 64
#define NB_SCAN ((NN + 255) / 256)   // 196

// ---------------- scratch (device globals; no allocation allowed) -------------
__device__ int      g_anynz;
__device__ int      g_cnt[NN];
__device__ int2     g_sc[NN];              // (start, cnt) packed
__device__ int      g_rank[EE];            // per-edge rank within its dst bucket
__device__ unsigned g_scan_pack[NB_SCAN];  // bits31-30: 0=none,1=agg,2=incl
__device__ unsigned g_scan_ctr;
__device__ int      g_csr_src[EE];
__device__ float    g_dinv[NN];
__device__ __half2  g_h1h[(size_t)NN * (HID / 2)];
__device__ __half2  g_o1h[(size_t)NN * (HID / 2)];  // relu'd layer-1 output, fp16
__device__ __half2  g_h2h[(size_t)NN * (LAT / 2)];

// ---------------- reset + dtype probe (fused) ---------------------------------
__global__ void k_reset_detect(const int* __restrict__ ei32, int* cnt, int n, int e,
                               int nblk) {
    int i = blockIdx.x * blockDim.x + threadIdx.x;
    if (i == 0) { g_anynz = 0; g_scan_ctr = 0; }
    if (i < n) cnt[i] = 0;
    if (i < nblk) g_scan_pack[i] = 0;
    if (i < 1024) {
        long long k = (long long)i * (e / 1024);
        if (ei32[2 * k + 1] != 0) atomicOr(&g_anynz, 1);
    }
}

// histogram + per-edge bucket rank (the atomic's return value)
__global__ void k_hist_rank(const int* __restrict__ ei32, int* cnt, int* rank, int e) {
    int i = blockIdx.x * blockDim.x + threadIdx.x;
    if (i >= e) return;
    int d;
    if (g_anynz == 0) d = ((const int2*)ei32)[(size_t)e + i].x;   // int64 lo word
    else              d = ei32[e + i];
    rank[i] = atomicAdd(&cnt[d], 1);
}

// ---------------- single-pass decoupled-lookback scan --------------------------
// writes packed (start,cnt) and dinv
__global__ void __launch_bounds__(256) k_scan_lookback(
    const int* __restrict__ cnt, int2* sc, float* dinv, int n)
{
    __shared__ int s[256];
    __shared__ int sbid;
    __shared__ int sprefix;
    const int tid = threadIdx.x;
    if (tid == 0) sbid = (int)atomicAdd(&g_scan_ctr, 1u);
    __syncthreads();
    const int bid = sbid;
    const int i = bid * 256 + tid;
    const int v = (i < n) ? cnt[i] : 0;

    s[tid] = v;
    __syncthreads();
    for (int off = 1; off < 256; off <<= 1) {
        int t = (tid >= off) ? s[tid - off] : 0;
        __syncthreads();
        s[tid] += t;
        __syncthreads();
    }
    const int total = s[255];

    if (tid == 0) {
        unsigned st = (bid == 0) ? 2u : 1u;
        atomicExch(&g_scan_pack[bid], (st << 30) | (unsigned)total);
    }

    if (tid < 32) {
        int prefix = 0;
        if (bid > 0) {
            int j = bid - 1;
            bool done = false;
            while (!done) {
                int idx = j - tid;
                unsigned p;
                if (idx >= 0) {
                    do { p = *(volatile unsigned*)&g_scan_pack[idx]; } while ((p >> 30) == 0u);
                } else {
                    p = (2u << 30);
                }
                unsigned stt = p >> 30;
                int val = (int)(p & 0x3FFFFFFFu);
                unsigned incl_mask = __ballot_sync(0xFFFFFFFFu, stt == 2u);
                int firstIncl = __ffs(incl_mask) - 1;
                int contrib;
                if (firstIncl >= 0) {
                    contrib = (tid <= firstIncl) ? val : 0;
                    done = true;
                } else {
                    contrib = (idx >= 0) ? val : 0;
                    j -= 32;
                }
#pragma unroll
                for (int o = 16; o; o >>= 1) contrib += __shfl_down_sync(0xFFFFFFFFu, contrib, o);
                prefix += __shfl_sync(0xFFFFFFFFu, contrib, 0);
            }
        }
        if (tid == 0) {
            sprefix = prefix;
            if (bid > 0)
                atomicExch(&g_scan_pack[bid], (2u << 30) | (unsigned)(prefix + total));
        }
    }
    __syncthreads();

    if (i < n) {
        sc[i] = make_int2(sprefix + s[tid] - v, v);
        dinv[i] = rsqrtf((float)(v + 1));
    }
}

// atomic-free bucket fill: position = start[dst] + precomputed rank
__global__ void k_fill_rank(const int* __restrict__ ei32, const int2* __restrict__ sc,
                            const int* __restrict__ rank, int* csr, int e) {
    int i = blockIdx.x * blockDim.x + threadIdx.x;
    if (i >= e) return;
    int s, d;
    if (g_anynz == 0) {            // int64: lo words
        s = ((const int2*)ei32)[i].x;
        d = ((const int2*)ei32)[(size_t)e + i].x;
    } else {                       // int32
        s = ei32[i];
        d = ei32[e + i];
    }
    csr[sc[d].x + rank[i]] = s;
}

// ---------------- fp16 MMA helper ---------------------------------------------
__device__ __forceinline__ void mma_f16(float4& d,
                                        uint32_t a0, uint32_t a1, uint32_t a2, uint32_t a3,
                                        uint32_t b0, uint32_t b1) {
    asm volatile(
        "mma.sync.aligned.m16n8k16.row.col.f32.f16.f16.f32 "
        "{%0,%1,%2,%3}, {%4,%5,%6,%7}, {%8,%9}, {%0,%1,%2,%3};"
        : "+f"(d.x), "+f"(d.y), "+f"(d.z), "+f"(d.w)
        : "r"(a0), "r"(a1), "r"(a2), "r"(a3), "r"(b0), "r"(b1));
}

// ---------------- GEMM1: fp32 in -> fp16 MMA -> fp16 out, [M,256]@[256,128] ---
__global__ void __launch_bounds__(256) gemm1_f16(
    const float* __restrict__ A, const float* __restrict__ B,
    __half2* __restrict__ Ch, int M, int K)   // K=256, N=128
{
    constexpr int BM = 128, BK = 32, BN = 128;
    constexpr int NT = BN / 16;              // 8 n8-tiles per warp
    __shared__ __half As[BM][BK + 8];
    __shared__ __half Bs[BK][BN + 8];

    const int tid    = threadIdx.x;
    const int warp   = tid >> 5;
    const int lane   = tid & 31;
    const int warp_m = warp & 3;
    const int warp_n = warp >> 2;
    const int m0     = blockIdx.x * BM;
    const int qr     = lane >> 2;
    const int qc     = lane & 3;

    const int am  = tid >> 3;
    const int ak4 = (tid & 7) << 2;
    const int bk  = tid >> 5;
    const int bn4 = (tid & 31) << 2;

    float4 acc[2][NT];
#pragma unroll
    for (int i = 0; i < 2; i++)
#pragma unroll
        for (int j = 0; j < NT; j++) acc[i][j] = make_float4(0.f, 0.f, 0.f, 0.f);

#pragma unroll
    for (int i = 0; i < 4; i++) {
        int m = am + i * 32;
        float4 v = make_float4(0.f, 0.f, 0.f, 0.f);
        if (m0 + m < M)
            v = *(const float4*)(A + (size_t)(m0 + m) * K + ak4);
        *(__half2*)&As[m][ak4]     = __floats2half2_rn(v.x, v.y);
        *(__half2*)&As[m][ak4 + 2] = __floats2half2_rn(v.z, v.w);
    }
#pragma unroll
    for (int i = 0; i < 4; i++) {
        int k = bk + i * 8;
        float4 v = *(const float4*)(B + (size_t)k * BN + bn4);
        *(__half2*)&Bs[k][bn4]     = __floats2half2_rn(v.x, v.y);
        *(__half2*)&Bs[k][bn4 + 2] = __floats2half2_rn(v.z, v.w);
    }
    __syncthreads();

    for (int k0 = 0; k0 < K; k0 += BK) {
        const bool has_next = (k0 + BK < K);
        float4 pa[4], pb[4];
        if (has_next) {
#pragma unroll
            for (int i = 0; i < 4; i++) {
                int m = am + i * 32;
                pa[i] = make_float4(0.f, 0.f, 0.f, 0.f);
                if (m0 + m < M)
                    pa[i] = *(const float4*)(A + (size_t)(m0 + m) * K + (k0 + BK) + ak4);
            }
#pragma unroll
            for (int i = 0; i < 4; i++) {
                int k = bk + i * 8;
                pb[i] = *(const float4*)(B + (size_t)(k0 + BK + k) * BN + bn4);
            }
        }

#pragma unroll
        for (int ks = 0; ks < 2; ks++) {
            const int c = ks * 16;
            uint32_t a[2][4];
#pragma unroll
            for (int mt = 0; mt < 2; mt++) {
                int r = warp_m * 32 + mt * 16 + qr;
                a[mt][0] = *(const uint32_t*)&As[r][c + 2 * qc];
                a[mt][1] = *(const uint32_t*)&As[r + 8][c + 2 * qc];
                a[mt][2] = *(const uint32_t*)&As[r][c + 2 * qc + 8];
                a[mt][3] = *(const uint32_t*)&As[r + 8][c + 2 * qc + 8];
            }
            uint32_t b[NT][2];
#pragma unroll
            for (int nt = 0; nt < NT; nt++) {
                int nn = warp_n * (NT * 8) + nt * 8 + qr;
                __half2 b0 = __halves2half2(Bs[c + 2 * qc][nn],     Bs[c + 2 * qc + 1][nn]);
                __half2 b1 = __halves2half2(Bs[c + 2 * qc + 8][nn], Bs[c + 2 * qc + 9][nn]);
                b[nt][0] = *(uint32_t*)&b0;
                b[nt][1] = *(uint32_t*)&b1;
            }
#pragma unroll
            for (int mt = 0; mt < 2; mt++)
#pragma unroll
                for (int nt = 0; nt < NT; nt++)
                    mma_f16(acc[mt][nt], a[mt][0], a[mt][1], a[mt][2], a[mt][3],
                            b[nt][0], b[nt][1]);
        }
        __syncthreads();

        if (has_next) {
#pragma unroll
            for (int i = 0; i < 4; i++) {
                int m = am + i * 32;
                *(__half2*)&As[m][ak4]     = __floats2half2_rn(pa[i].x, pa[i].y);
                *(__half2*)&As[m][ak4 + 2] = __floats2half2_rn(pa[i].z, pa[i].w);
            }
#pragma unroll
            for (int i = 0; i < 4; i++) {
                int k = bk + i * 8;
                *(__half2*)&Bs[k][bn4]     = __floats2half2_rn(pb[i].x, pb[i].y);
                *(__half2*)&Bs[k][bn4 + 2] = __floats2half2_rn(pb[i].z, pb[i].w);
            }
            __syncthreads();
        }
    }

#pragma unroll
    for (int mt = 0; mt < 2; mt++) {
        int row = m0 + warp_m * 32 + mt * 16 + qr;
#pragma unroll
        for (int nt = 0; nt < NT; nt++) {
            int col2 = (warp_n * (NT * 8) + nt * 8 + 2 * qc) >> 1;
            if (row < M)
                Ch[(size_t)row * (BN / 2) + col2] = __floats2half2_rn(acc[mt][nt].x, acc[mt][nt].y);
            if (row + 8 < M)
                Ch[(size_t)(row + 8) * (BN / 2) + col2] = __floats2half2_rn(acc[mt][nt].z, acc[mt][nt].w);
        }
    }
}

// ---------------- GEMM2: fp16 in (relu'd o1) @ fp32 W2 -> fp16 h2 -------------
// [M,128] @ [128,64]; BM=128, BK=32, BN=64; row range [m_lo, m_hi).
__global__ void __launch_bounds__(256) gemm2_f16(
    const __half2* __restrict__ Ah, const float* __restrict__ B,
    __half2* __restrict__ Ch, int m_lo, int m_hi)
{
    constexpr int BM = 128, BK = 32, BN = 64, K = 128;
    constexpr int NT = BN / 16;              // 4 n8-tiles per warp
    __shared__ __half As[BM][BK + 8];
    __shared__ __half Bs[BK][BN + 8];

    const int tid    = threadIdx.x;
    const int warp   = tid >> 5;
    const int lane   = tid & 31;
    const int warp_m = warp & 3;
    const int warp_n = warp >> 2;
    const int m0     = m_lo + blockIdx.x * BM;
    const int qr     = lane >> 2;
    const int qc     = lane & 3;

    const int am = tid >> 1;                 // A row (2 threads per row)
    const int aq = (tid & 1) << 3;           // half2 offset within 16-half2 tile row: 0 or 8
    const int bkr = tid >> 4;                // B k row (stride 16 rows per 256 thr? no:)
    const int bn4 = (tid & 15) << 2;         // B n offset (float4)

    float4 acc[2][NT];
#pragma unroll
    for (int i = 0; i < 2; i++)
#pragma unroll
        for (int j = 0; j < NT; j++) acc[i][j] = make_float4(0.f, 0.f, 0.f, 0.f);

    // ---- tile 0 ----
    // A: 128 rows x 16 half2; per thread: one uint4 (4 half2) x2 -> 8 half2
#pragma unroll
    for (int i = 0; i < 2; i++) {
        int q2 = aq + i * 4;                 // half2 offset 0,4 or 8,12
        uint4 v = make_uint4(0, 0, 0, 0);
        if (m0 + am < m_hi)
            v = *(const uint4*)(Ah + (size_t)(m0 + am) * 64 + q2);
        *(uint4*)&As[am][q2 * 2] = v;
    }
    // B: 32 rows x 64 floats; per thread: float4 x2
#pragma unroll
    for (int i = 0; i < 2; i++) {
        int k = bkr + i * 16;
        float4 v = *(const float4*)(B + (size_t)k * BN + bn4);
        *(__half2*)&Bs[k][bn4]     = __floats2half2_rn(v.x, v.y);
        *(__half2*)&Bs[k][bn4 + 2] = __floats2half2_rn(v.z, v.w);
    }
    __syncthreads();

    for (int k0 = 0; k0 < K; k0 += BK) {
        const bool has_next = (k0 + BK < K);
        uint4 pa[2]; float4 pb[2];
        if (has_next) {
#pragma unroll
            for (int i = 0; i < 2; i++) {
                int q2 = aq + i * 4;
                pa[i] = make_uint4(0, 0, 0, 0);
                if (m0 + am < m_hi)
                    pa[i] = *(const uint4*)(Ah + (size_t)(m0 + am) * 64 + (k0 + BK) / 2 + q2);
            }
#pragma unroll
            for (int i = 0; i < 2; i++) {
                int k = bkr + i * 16;
                pb[i] = *(const float4*)(B + (size_t)(k0 + BK + k) * BN + bn4);
            }
        }

#pragma unroll
        for (int ks = 0; ks < 2; ks++) {
            const int c = ks * 16;
            uint32_t a[2][4];
#pragma unroll
            for (int mt = 0; mt < 2; mt++) {
                int r = warp_m * 32 + mt * 16 + qr;
                a[mt][0] = *(const uint32_t*)&As[r][c + 2 * qc];
                a[mt][1] = *(const uint32_t*)&As[r + 8][c + 2 * qc];
                a[mt][2] = *(const uint32_t*)&As[r][c + 2 * qc + 8];
                a[mt][3] = *(const uint32_t*)&As[r + 8][c + 2 * qc + 8];
            }
            uint32_t b[NT][2];
#pragma unroll
            for (int nt = 0; nt < NT; nt++) {
                int nn = warp_n * (NT * 8) + nt * 8 + qr;
                __half2 b0 = __halves2half2(Bs[c + 2 * qc][nn],     Bs[c + 2 * qc + 1][nn]);
                __half2 b1 = __halves2half2(Bs[c + 2 * qc + 8][nn], Bs[c + 2 * qc + 9][nn]);
                b[nt][0] = *(uint32_t*)&b0;
                b[nt][1] = *(uint32_t*)&b1;
            }
#pragma unroll
            for (int mt = 0; mt < 2; mt++)
#pragma unroll
                for (int nt = 0; nt < NT; nt++)
                    mma_f16(acc[mt][nt], a[mt][0], a[mt][1], a[mt][2], a[mt][3],
                            b[nt][0], b[nt][1]);
        }
        __syncthreads();

        if (has_next) {
#pragma unroll
            for (int i = 0; i < 2; i++)
                *(uint4*)&As[am][(aq + i * 4) * 2] = pa[i];
#pragma unroll
            for (int i = 0; i < 2; i++) {
                int k = bkr + i * 16;
                *(__half2*)&Bs[k][bn4]     = __floats2half2_rn(pb[i].x, pb[i].y);
                *(__half2*)&Bs[k][bn4 + 2] = __floats2half2_rn(pb[i].z, pb[i].w);
            }
            __syncthreads();
        }
    }

#pragma unroll
    for (int mt = 0; mt < 2; mt++) {
        int row = m0 + warp_m * 32 + mt * 16 + qr;
#pragma unroll
        for (int nt = 0; nt < NT; nt++) {
            int col2 = (warp_n * (NT * 8) + nt * 8 + 2 * qc) >> 1;
            if (row < m_hi)
                Ch[(size_t)row * (BN / 2) + col2] = __floats2half2_rn(acc[mt][nt].x, acc[mt][nt].y);
            if (row + 8 < m_hi)
                Ch[(size_t)(row + 8) * (BN / 2) + col2] = __floats2half2_rn(acc[mt][nt].z, acc[mt][nt].w);
        }
    }
}

// ---------------- agg128: fp16 gather, fp32 accum, fused relu, fp16 out -------
__global__ void __launch_bounds__(256) k_agg128(
    const int2* __restrict__ sc, const int* __restrict__ csr,
    const float* __restrict__ dinv, const __half2* __restrict__ h,
    const float* __restrict__ bias, __half2* __restrict__ outh,
    int n_lo, int n_hi)
{
    int d = n_lo + ((blockIdx.x * blockDim.x + threadIdx.x) >> 5);
    int lane = threadIdx.x & 31;
    if (d >= n_hi) return;
    float dd = dinv[d];
    int2 scd = sc[d];
    int beg = scd.x, num = scd.y;

    uint2 raw = *(const uint2*)(h + (size_t)d * 64 + lane * 2);
    float2 p0 = __half22float2(*(__half2*)&raw.x);
    float2 p1 = __half22float2(*(__half2*)&raw.y);
    float4 bv = *(const float4*)(bias + lane * 4);
    float sd = dd * dd;
    float4 acc;
    acc.x = fmaf(sd, p0.x, bv.x); acc.y = fmaf(sd, p0.y, bv.y);
    acc.z = fmaf(sd, p1.x, bv.z); acc.w = fmaf(sd, p1.y, bv.w);

#pragma unroll 4
    for (int j = 0; j < num; j++) {
        int s = __ldg(&csr[beg + j]);
        float nrm = dd * __ldg(&dinv[s]);
        uint2 r = *(const uint2*)(h + (size_t)s * 64 + lane * 2);
        float2 v0 = __half22float2(*(__half2*)&r.x);
        float2 v1 = __half22float2(*(__half2*)&r.y);
        acc.x = fmaf(nrm, v0.x, acc.x); acc.y = fmaf(nrm, v0.y, acc.y);
        acc.z = fmaf(nrm, v1.x, acc.z); acc.w = fmaf(nrm, v1.y, acc.w);
    }
    // fused relu + fp16 store
    uint2 o;
    __half2 o0 = __floats2half2_rn(fmaxf(acc.x, 0.f), fmaxf(acc.y, 0.f));
    __half2 o1 = __floats2half2_rn(fmaxf(acc.z, 0.f), fmaxf(acc.w, 0.f));
    o.x = *(uint32_t*)&o0; o.y = *(uint32_t*)&o1;
    *(uint2*)(outh + (size_t)d * 64 + lane * 2) = o;
}

// ---------------- agg64: fp16 gather + fused final relu, fp32 out -------------
__global__ void __launch_bounds__(256) k_agg64_relu(
    const int2* __restrict__ sc, const int* __restrict__ csr,
    const float* __restrict__ dinv, const __half2* __restrict__ h,
    const float* __restrict__ bias, float* __restrict__ out, int n)
{
    int d = (blockIdx.x * blockDim.x + threadIdx.x) >> 5;
    int lane = threadIdx.x & 31;
    if (d >= n) return;
    float dd = dinv[d];
    int2 scd = sc[d];
    int beg = scd.x, num = scd.y;

    float2 hv = __half22float2(h[(size_t)d * 32 + lane]);
    float2 bv = *(const float2*)(bias + lane * 2);
    float sd = dd * dd;
    float2 acc;
    acc.x = fmaf(sd, hv.x, bv.x); acc.y = fmaf(sd, hv.y, bv.y);

#pragma unroll 4
    for (int j = 0; j < num; j++) {
        int s = __ldg(&csr[beg + j]);
        float nrm = dd * __ldg(&dinv[s]);
        float2 v = __half22float2(__ldg(h + (size_t)s * 32 + lane));
        acc.x = fmaf(nrm, v.x, acc.x); acc.y = fmaf(nrm, v.y, acc.y);
    }
    acc.x = fmaxf(acc.x, 0.f);
    acc.y = fmaxf(acc.y, 0.f);
    *(float2*)(out + (size_t)d * 64 + lane * 2) = acc;
}

// ==============================================================================
extern "C" void kernel_launch(void* const* d_in, const int* in_sizes, int n_in,
                              void* d_out, int out_size)
{
    const float* x    = (const float*)d_in[0];   // [N, 256]
    const int*   ei32 = (const int*)d_in[1];     // [2, E] int32 OR int64 (probed)
    const float* W1   = (const float*)d_in[2];   // [256, 128]
    const float* b1   = (const float*)d_in[3];   // [128]
    const float* W2   = (const float*)d_in[4];   // [128, 64]
    const float* b2   = (const float*)d_in[5];   // [64]
    float*       out  = (float*)d_out;           // [N, 64]

    const int n = in_sizes[0] / IN_CH;   // 50000
    const int e = in_sizes[1] / 2;       // 800000

    int *cnt, *rank, *csr;
    int2 *sc;
    float *dinv;
    __half2 *h1h, *o1h, *h2h;
    cudaGetSymbolAddress((void**)&cnt,  g_cnt);
    cudaGetSymbolAddress((void**)&sc,   g_sc);
    cudaGetSymbolAddress((void**)&rank, g_rank);
    cudaGetSymbolAddress((void**)&csr,  g_csr_src);
    cudaGetSymbolAddress((void**)&dinv, g_dinv);
    cudaGetSymbolAddress((void**)&h1h,  g_h1h);
    cudaGetSymbolAddress((void**)&o1h,  g_o1h);
    cudaGetSymbolAddress((void**)&h2h,  g_h2h);

    // side stream + events, created once on the first (uncaptured) call
    static cudaStream_t s2 = nullptr;
    static cudaEvent_t  ev_fork = nullptr, ev_csr = nullptr,
                        ev_g1 = nullptr, ev_c1 = nullptr;
    if (s2 == nullptr) {
        cudaStreamCreateWithFlags(&s2, cudaStreamNonBlocking);
        cudaEventCreateWithFlags(&ev_fork, cudaEventDisableTiming);
        cudaEventCreateWithFlags(&ev_csr,  cudaEventDisableTiming);
        cudaEventCreateWithFlags(&ev_g1,   cudaEventDisableTiming);
        cudaEventCreateWithFlags(&ev_c1,   cudaEventDisableTiming);
    }

    const int T = 256;
    const int nb = (n + T - 1) / T;
    const int eb = (e + T - 1) / T;
    const int half = ((n / 2) + 127) & ~127;

    // ---- fork: CSR build chain on s2, concurrent with GEMM1 on stream 0 ----
    cudaEventRecord(ev_fork, 0);
    cudaStreamWaitEvent(s2, ev_fork, 0);

    k_reset_detect <<<nb, T, 0, s2>>>(ei32, cnt, n, e, nb);
    k_hist_rank    <<<eb, T, 0, s2>>>(ei32, cnt, rank, e);
    k_scan_lookback<<<nb, T, 0, s2>>>(cnt, sc, dinv, n);
    k_fill_rank    <<<eb, T, 0, s2>>>(ei32, sc, rank, csr, e);
    cudaEventRecord(ev_csr, s2);

    // GEMM1 (fp16 MMA) on the main stream, overlapping the CSR build
    gemm1_f16<<<(n + 127) / 128, 256>>>(x, W1, h1h, n, IN_CH);
    cudaEventRecord(ev_g1, 0);

    // ---- chunked layer-1 agg + layer-2 GEMM, two independent chains --------
    cudaStreamWaitEvent(0, ev_csr, 0);
    k_agg128<<<(half * 32 + T - 1) / T, T>>>(sc, csr, dinv, h1h, b1, o1h, 0, half);
    gemm2_f16<<<half / 128, 256>>>(o1h, W2, h2h, 0, half);

    cudaStreamWaitEvent(s2, ev_g1, 0);
    k_agg128<<<((n - half) * 32 + T - 1) / T, T, 0, s2>>>(sc, csr, dinv, h1h, b1, o1h, half, n);
    gemm2_f16<<<(n - half + 127) / 128, 256, 0, s2>>>(o1h, W2, h2h, half, n);
    cudaEventRecord(ev_c1, s2);

    // ---- join: agg64 needs the full h2 ----
    cudaStreamWaitEvent(0, ev_c1, 0);
    k_agg64_relu<<<(n * 32 + T - 1) / T, T>>>(sc, csr, dinv, h2h, b2, out, n);
}